// round 1
// baseline (speedup 1.0000x reference)
#include <cuda_runtime.h>
#include <math.h>

#define B_ 2
#define S_ 2048
#define D_ 768
#define H_ 12
#define HD_ 64
#define FF_ 3072
#define L_ 12
#define M_ (B_*S_)   // 4096 rows

// ---------------- scratch (device globals; no allocation allowed) ----------
__device__ float g_x[M_*D_];
__device__ float g_t[M_*D_];
__device__ float g_q[M_*D_];
__device__ float g_k[M_*D_];
__device__ float g_v[M_*D_];
__device__ float g_a[M_*D_];
__device__ float g_h[M_*FF_];

// ---------------- helpers ----------------
__device__ __forceinline__ float block_reduce_sum(float v, float* sh) {
    int t = threadIdx.x;
    sh[t] = v; __syncthreads();
    for (int off = 128; off; off >>= 1) {
        if (t < off) sh[t] += sh[t + off];
        __syncthreads();
    }
    float r = sh[0];
    __syncthreads();
    return r;
}

// ---------------- embedding + layernorm (fused) ----------------
__global__ void embed_ln_kernel(const int* __restrict__ ids,
                                const float* __restrict__ we,
                                const float* __restrict__ pe,
                                const float* __restrict__ te,
                                const float* __restrict__ g,
                                const float* __restrict__ b) {
    __shared__ float sh[256];
    int row = blockIdx.x;              // b*S + s
    int s = row % S_;
    int id = ids[row];
    float vals[3];
    float lsum = 0.f;
#pragma unroll
    for (int e = 0; e < 3; e++) {
        int d = threadIdx.x + e * 256;
        vals[e] = we[(size_t)id * D_ + d] + pe[(size_t)(s + 2) * D_ + d] + te[d];
        lsum += vals[e];
    }
    float mean = block_reduce_sum(lsum, sh) * (1.0f / D_);
    float lsq = 0.f;
#pragma unroll
    for (int e = 0; e < 3; e++) { float dv = vals[e] - mean; lsq += dv * dv; }
    float var = block_reduce_sum(lsq, sh) * (1.0f / D_);
    float inv = rsqrtf(var + 1e-5f);
#pragma unroll
    for (int e = 0; e < 3; e++) {
        int d = threadIdx.x + e * 256;
        g_x[(size_t)row * D_ + d] = (vals[e] - mean) * inv * g[d] + b[d];
    }
}

// ---------------- layernorm: out = LN(in) ----------------
__global__ void ln_kernel(const float* __restrict__ in,
                          const float* __restrict__ g,
                          const float* __restrict__ b,
                          float* __restrict__ out) {
    __shared__ float sh[256];
    int row = blockIdx.x;
    const float* r = in + (size_t)row * D_;
    float vals[3];
    float lsum = 0.f;
#pragma unroll
    for (int e = 0; e < 3; e++) {
        vals[e] = r[threadIdx.x + e * 256];
        lsum += vals[e];
    }
    float mean = block_reduce_sum(lsum, sh) * (1.0f / D_);
    float lsq = 0.f;
#pragma unroll
    for (int e = 0; e < 3; e++) { float dv = vals[e] - mean; lsq += dv * dv; }
    float var = block_reduce_sum(lsq, sh) * (1.0f / D_);
    float inv = rsqrtf(var + 1e-5f);
#pragma unroll
    for (int e = 0; e < 3; e++) {
        int d = threadIdx.x + e * 256;
        out[(size_t)row * D_ + d] = (vals[e] - mean) * inv * g[d] + b[d];
    }
}

// ---------------- tiled SGEMM: C = epi(A[MxK] @ W[KxN] + bias [+ res]) -----
// epi: 0 = none, 1 = exact gelu, 2 = add residual
#define BM 64
#define BN 64
#define BK 16
__global__ void gemm_kernel(const float* __restrict__ A,
                            const float* __restrict__ W,
                            const float* __restrict__ bias,
                            const float* __restrict__ res,
                            float* __restrict__ C,
                            int M, int N, int K, int epi) {
    __shared__ float As[BK][BM + 1];
    __shared__ float Bs[BK][BN];
    int t = threadIdx.x;
    int tx = t & 15, ty = t >> 4;
    int m0 = blockIdx.y * BM, n0 = blockIdx.x * BN;
    float acc[4][4] = {};
    for (int k0 = 0; k0 < K; k0 += BK) {
#pragma unroll
        for (int e = 0; e < 4; e++) {
            int lin = t + e * 256;
            int m = lin >> 4, kk = lin & 15;
            As[kk][m] = A[(size_t)(m0 + m) * K + k0 + kk];
        }
#pragma unroll
        for (int e = 0; e < 4; e++) {
            int lin = t + e * 256;
            int kk = lin >> 6, n = lin & 63;
            Bs[kk][n] = W[(size_t)(k0 + kk) * N + n0 + n];
        }
        __syncthreads();
#pragma unroll
        for (int kk = 0; kk < BK; kk++) {
            float a[4], bv[4];
#pragma unroll
            for (int i = 0; i < 4; i++) a[i] = As[kk][ty * 4 + i];
#pragma unroll
            for (int j = 0; j < 4; j++) bv[j] = Bs[kk][tx * 4 + j];
#pragma unroll
            for (int i = 0; i < 4; i++)
#pragma unroll
                for (int j = 0; j < 4; j++) acc[i][j] += a[i] * bv[j];
        }
        __syncthreads();
    }
#pragma unroll
    for (int i = 0; i < 4; i++) {
        int m = m0 + ty * 4 + i;
#pragma unroll
        for (int j = 0; j < 4; j++) {
            int n = n0 + tx * 4 + j;
            float c = acc[i][j] + bias[n];
            if (epi == 1) {
                c = 0.5f * c * (1.0f + erff(c * 0.70710678118654752f));
            } else if (epi == 2) {
                c += res[(size_t)m * N + n];
            }
            C[(size_t)m * N + n] = c;
        }
    }
}

// ---------------- banded attention: warp per query, online softmax ---------
__global__ void attn_kernel(const float* __restrict__ q,
                            const float* __restrict__ k,
                            const float* __restrict__ v,
                            const float* __restrict__ mask,
                            float* __restrict__ out,
                            int half) {
    int warp = (blockIdx.x * blockDim.x + threadIdx.x) >> 5;
    int lane = threadIdx.x & 31;
    // warp -> (b, h, s)
    int s = warp % S_;
    int bh = warp / S_;
    int h = bh % H_;
    int b = bh / H_;

    const float* qrow = q + ((size_t)(b * S_ + s) * D_) + h * HD_;
    float2 qv = *(const float2*)(qrow + 2 * lane);
    const float scale = 0.125f;  // 1/sqrt(64)
    float q0 = qv.x * scale, q1 = qv.y * scale;

    int j0 = s - half; if (j0 < 0) j0 = 0;
    int j1 = s + half; if (j1 > S_ - 1) j1 = S_ - 1;

    float m = -1e30f, l = 0.f, acc0 = 0.f, acc1 = 0.f;
    for (int j = j0; j <= j1; j++) {
        const float* krow = k + ((size_t)(b * S_ + j) * D_) + h * HD_;
        float2 kv = *(const float2*)(krow + 2 * lane);
        float part = q0 * kv.x + q1 * kv.y;
#pragma unroll
        for (int off = 16; off; off >>= 1)
            part += __shfl_xor_sync(0xffffffffu, part, off);
        float sc = part + (1.0f - mask[b * S_ + j]) * (-1e9f);
        float mn = fmaxf(m, sc);
        float so = __expf(m - mn);
        float p = __expf(sc - mn);
        l = l * so + p;
        const float* vrow = v + ((size_t)(b * S_ + j) * D_) + h * HD_;
        float2 vv = *(const float2*)(vrow + 2 * lane);
        acc0 = acc0 * so + p * vv.x;
        acc1 = acc1 * so + p * vv.y;
        m = mn;
    }
    float inv = 1.0f / l;
    float* orow = out + ((size_t)(b * S_ + s) * D_) + h * HD_;
    orow[2 * lane]     = acc0 * inv;
    orow[2 * lane + 1] = acc1 * inv;
}

// ---------------- top head ----------------
__global__ void top_kernel(const float* __restrict__ fts,
                           const float* __restrict__ Wtop,
                           const float* __restrict__ btop,
                           float* __restrict__ out) {
    __shared__ float sh[256];
    int b = blockIdx.x;
    const float* cls = g_x + (size_t)b * S_ * D_;   // row (b, 0)
    float part = 0.f;
    for (int d = threadIdx.x; d < D_; d += 256) part += cls[d] * Wtop[d];
    float r = block_reduce_sum(part, sh);
    if (threadIdx.x == 0)
        out[b] = r + fts[b] * Wtop[D_] + btop[0];
}

// ---------------- host driver ----------------
extern "C" void kernel_launch(void* const* d_in, const int* in_sizes, int n_in,
                              void* d_out, int out_size) {
    const int*   ids     = (const int*)  d_in[0];
    const float* mask    = (const float*)d_in[1];
    const float* fts     = (const float*)d_in[2];
    const float* we      = (const float*)d_in[3];
    const float* pe      = (const float*)d_in[4];
    const float* te      = (const float*)d_in[5];
    const float* ln_eg   = (const float*)d_in[6];
    const float* ln_eb   = (const float*)d_in[7];
    const float* Wq      = (const float*)d_in[8];
    const float* bq      = (const float*)d_in[9];
    const float* Wk      = (const float*)d_in[10];
    const float* bk      = (const float*)d_in[11];
    const float* Wv      = (const float*)d_in[12];
    const float* bv      = (const float*)d_in[13];
    const float* Wo      = (const float*)d_in[14];
    const float* bo      = (const float*)d_in[15];
    const float* ln1g    = (const float*)d_in[16];
    const float* ln1b    = (const float*)d_in[17];
    const float* W1      = (const float*)d_in[18];
    const float* b1      = (const float*)d_in[19];
    const float* W2      = (const float*)d_in[20];
    const float* b2      = (const float*)d_in[21];
    const float* ln2g    = (const float*)d_in[22];
    const float* ln2b    = (const float*)d_in[23];
    const float* Wtop    = (const float*)d_in[24];
    const float* btop    = (const float*)d_in[25];
    float* out = (float*)d_out;

    float *x, *tt, *qp, *kp, *vp, *ap, *hp;
    cudaGetSymbolAddress((void**)&x,  g_x);
    cudaGetSymbolAddress((void**)&tt, g_t);
    cudaGetSymbolAddress((void**)&qp, g_q);
    cudaGetSymbolAddress((void**)&kp, g_k);
    cudaGetSymbolAddress((void**)&vp, g_v);
    cudaGetSymbolAddress((void**)&ap, g_a);
    cudaGetSymbolAddress((void**)&hp, g_h);

    static const int halves[L_] = {16,16,32,32,64,64,128,128,256,256,256,256};

    // embedding + LN
    embed_ln_kernel<<<M_, 256>>>(ids, we, pe, te, ln_eg, ln_eb);

    dim3 gD(D_ / BN, M_ / BM);     // N=768 gemms
    dim3 gF(FF_ / BN, M_ / BM);    // N=3072 gemm

    for (int i = 0; i < L_; i++) {
        const float* wq = Wq + (size_t)i * D_ * D_;
        const float* wk = Wk + (size_t)i * D_ * D_;
        const float* wv = Wv + (size_t)i * D_ * D_;
        const float* wo = Wo + (size_t)i * D_ * D_;
        const float* w1 = W1 + (size_t)i * D_ * FF_;
        const float* w2 = W2 + (size_t)i * FF_ * D_;

        gemm_kernel<<<gD, 256>>>(x, wq, bq + (size_t)i * D_, nullptr, qp, M_, D_, D_, 0);
        gemm_kernel<<<gD, 256>>>(x, wk, bk + (size_t)i * D_, nullptr, kp, M_, D_, D_, 0);
        gemm_kernel<<<gD, 256>>>(x, wv, bv + (size_t)i * D_, nullptr, vp, M_, D_, D_, 0);

        int nwarps = B_ * H_ * S_;
        attn_kernel<<<nwarps / 8, 256>>>(qp, kp, vp, mask, ap, halves[i]);

        // t = x + a @ Wo + bo ; x = LN(t)
        gemm_kernel<<<gD, 256>>>(ap, wo, bo + (size_t)i * D_, x, tt, M_, D_, D_, 2);
        ln_kernel<<<M_, 256>>>(tt, ln1g + (size_t)i * D_, ln1b + (size_t)i * D_, x);

        // h = gelu(x @ W1 + b1)
        gemm_kernel<<<gF, 256>>>(x, w1, b1 + (size_t)i * FF_, nullptr, hp, M_, FF_, D_, 1);
        // t = x + h @ W2 + b2 ; x = LN(t)
        gemm_kernel<<<gD, 256>>>(hp, w2, b2 + (size_t)i * D_, x, tt, M_, D_, FF_, 2);
        ln_kernel<<<M_, 256>>>(tt, ln2g + (size_t)i * D_, ln2b + (size_t)i * D_, x);
    }

    top_kernel<<<B_, 256>>>(fts, Wtop, btop, out);
}

// round 4
// speedup vs baseline: 1.6036x; 1.6036x over previous
#include <cuda_runtime.h>
#include <cuda_bf16.h>
#include <math.h>
#include <stdint.h>

#define B_ 2
#define S_ 2048
#define D_ 768
#define H_ 12
#define HD_ 64
#define FF_ 3072
#define L_ 12
#define M_ (B_*S_)   // 4096 rows

// ---------------- scratch (device globals; no allocation allowed) ----------
__device__ float g_x[M_*D_];
__device__ float g_t[M_*D_];
__device__ float g_q[M_*D_];
__device__ float g_k[M_*D_];
__device__ float g_v[M_*D_];
__device__ float g_a[M_*D_];
__device__ float g_h[M_*FF_];

// bf16 split buffers (hi/lo)
__device__ __align__(16) __nv_bfloat16 g_xs_hi[M_*D_],  g_xs_lo[M_*D_];
__device__ __align__(16) __nv_bfloat16 g_as_hi[M_*D_],  g_as_lo[M_*D_];
__device__ __align__(16) __nv_bfloat16 g_hs_hi[M_*FF_], g_hs_lo[M_*FF_];
// transposed+split weights for one layer at a time: [N][K] bf16
__device__ __align__(16) __nv_bfloat16 g_wtq_hi[D_*D_],  g_wtq_lo[D_*D_];
__device__ __align__(16) __nv_bfloat16 g_wtk_hi[D_*D_],  g_wtk_lo[D_*D_];
__device__ __align__(16) __nv_bfloat16 g_wtv_hi[D_*D_],  g_wtv_lo[D_*D_];
__device__ __align__(16) __nv_bfloat16 g_wto_hi[D_*D_],  g_wto_lo[D_*D_];
__device__ __align__(16) __nv_bfloat16 g_wt1_hi[FF_*D_], g_wt1_lo[FF_*D_];  // N=3072,K=768
__device__ __align__(16) __nv_bfloat16 g_wt2_hi[D_*FF_], g_wt2_lo[D_*FF_];  // N=768,K=3072

// ---------------- PTX helpers (base-target safe: Ampere-era ops only) -----
__device__ __forceinline__ uint32_t smem_u32(const void* p) {
    uint32_t a;
    asm("{ .reg .u64 t; cvta.to.shared.u64 t, %1; cvt.u32.u64 %0, t; }" : "=r"(a) : "l"(p));
    return a;
}
__device__ __forceinline__ void cp16(uint32_t s, const void* g) {
    asm volatile("cp.async.cg.shared.global [%0], [%1], 16;" :: "r"(s), "l"(g));
}
#define CP_COMMIT()  asm volatile("cp.async.commit_group;" ::: "memory")
#define CP_WAIT(n)   asm volatile("cp.async.wait_group %0;" :: "n"(n) : "memory")

__device__ __forceinline__ void ldm4(uint32_t* r, uint32_t addr) {
    asm volatile("ldmatrix.sync.aligned.m8n8.x4.shared.b16 {%0,%1,%2,%3}, [%4];"
        : "=r"(r[0]), "=r"(r[1]), "=r"(r[2]), "=r"(r[3]) : "r"(addr));
}
__device__ __forceinline__ void mma16816(float* c, const uint32_t* a, uint32_t b0, uint32_t b1) {
    asm volatile("mma.sync.aligned.m16n8k16.row.col.f32.bf16.bf16.f32 "
        "{%0,%1,%2,%3}, {%4,%5,%6,%7}, {%8,%9}, {%0,%1,%2,%3};"
        : "+f"(c[0]), "+f"(c[1]), "+f"(c[2]), "+f"(c[3])
        : "r"(a[0]), "r"(a[1]), "r"(a[2]), "r"(a[3]), "r"(b0), "r"(b1));
}

// ---------------- split kernels ----------------
__global__ void split_kernel(const float* __restrict__ in,
                             __nv_bfloat16* __restrict__ hi,
                             __nv_bfloat16* __restrict__ lo, int n) {
    for (int i = blockIdx.x * blockDim.x + threadIdx.x; i < n; i += gridDim.x * blockDim.x) {
        float x = in[i];
        __nv_bfloat16 h = __float2bfloat16(x);
        __nv_bfloat16 l = __float2bfloat16(x - __bfloat162float(h));
        hi[i] = h; lo[i] = l;
    }
}

// W[K][N] f32 -> T[N][K] bf16 hi/lo
__global__ void tsplit_kernel(const float* __restrict__ W,
                              __nv_bfloat16* __restrict__ Thi,
                              __nv_bfloat16* __restrict__ Tlo, int K, int N) {
    __shared__ float t[32][33];
    int k0 = blockIdx.y * 32, n0 = blockIdx.x * 32;
    int tx = threadIdx.x & 31, ty = threadIdx.x >> 5;  // 32 x 8
#pragma unroll
    for (int i = 0; i < 4; i++)
        t[ty + i * 8][tx] = W[(size_t)(k0 + ty + i * 8) * N + n0 + tx];
    __syncthreads();
#pragma unroll
    for (int i = 0; i < 4; i++) {
        float v = t[tx][ty + i * 8];
        __nv_bfloat16 h = __float2bfloat16(v);
        __nv_bfloat16 l = __float2bfloat16(v - __bfloat162float(h));
        size_t o = (size_t)(n0 + ty + i * 8) * K + k0 + tx;
        Thi[o] = h; Tlo[o] = l;
    }
}

// ---------------- mma.sync GEMM: C[M,N] = epi(Ahl @ Bhl^T + bias) ---------
// A: [M,K] bf16 hi/lo K-major. B: [N,K] bf16 hi/lo K-major (pre-transposed W).
// CTA tile 128x128, BK=32, double-buffered cp.async, 3-MMA bf16x2 split.
// SMEM row pitch 80 bytes (40 bf16) -> conflict-free ldmatrix.
#define PITCH   80
#define TILEB   (128*PITCH)        // 10240
#define STAGE   (4*TILEB)          // 40960 (Ah, Al, Bh, Bl)
#define GSMEM   (2*STAGE)          // 81920

__device__ __forceinline__ void load_chunk(uint32_t sbase,
                                           const __nv_bfloat16* pAh, const __nv_bfloat16* pAl,
                                           const __nv_bfloat16* pBh, const __nv_bfloat16* pBl,
                                           int K, int tid) {
    // 4 tiles x 512 16B ops = 2048; 256 threads x 8
#pragma unroll
    for (int e = 0; e < 2; e++) {
        int idx = tid + e * 256;
        int r = idx >> 2, ch = idx & 3;
        uint32_t so = r * PITCH + ch * 16;
        size_t go = (size_t)r * K + ch * 8;
        cp16(sbase + 0*TILEB + so, pAh + go);
        cp16(sbase + 1*TILEB + so, pAl + go);
        cp16(sbase + 2*TILEB + so, pBh + go);
        cp16(sbase + 3*TILEB + so, pBl + go);
    }
}

__device__ __forceinline__ float gelu_f(float c) {
    return 0.5f * c * (1.0f + erff(c * 0.70710678118654752f));
}

__global__ void __launch_bounds__(256, 1)
gemm_tc(const __nv_bfloat16* __restrict__ Ahi, const __nv_bfloat16* __restrict__ Alo,
        const __nv_bfloat16* __restrict__ Bhi, const __nv_bfloat16* __restrict__ Blo,
        const float* __restrict__ bias, const float* __restrict__ res,
        float* __restrict__ C, int N, int K, int epi) {
    extern __shared__ __align__(16) char smem[];
    uint32_t sb = smem_u32(smem);
    int tid = threadIdx.x, wid = tid >> 5, lane = tid & 31;
    int wm = wid >> 2, wn = wid & 3;       // warp tile: 64 rows x 32 cols
    int m0 = blockIdx.y * 128, n0 = blockIdx.x * 128;

    const __nv_bfloat16* pAh = Ahi + (size_t)m0 * K;
    const __nv_bfloat16* pAl = Alo + (size_t)m0 * K;
    const __nv_bfloat16* pBh = Bhi + (size_t)n0 * K;
    const __nv_bfloat16* pBl = Blo + (size_t)n0 * K;

    float acc[4][4][4] = {};

    const int NC = K / 32;
    load_chunk(sb, pAh, pAl, pBh, pBl, K, tid);
    CP_COMMIT();

    // ldmatrix base addressing (per lane, within a tile):
    // row = base + (lane & 15), chunk16 = ks*32 + (lane>>4)*16
    int lrow = lane & 15;
    int lch  = (lane >> 4) * 16;

    for (int c = 0; c < NC; c++) {
        uint32_t st = sb + (c & 1) * STAGE;
        if (c + 1 < NC) {
            load_chunk(sb + ((c + 1) & 1) * STAGE,
                       pAh + (c+1)*32, pAl + (c+1)*32,
                       pBh + (c+1)*32, pBl + (c+1)*32, K, tid);
            CP_COMMIT();
            CP_WAIT(1);
        } else {
            CP_WAIT(0);
        }
        __syncthreads();

#pragma unroll
        for (int ks = 0; ks < 2; ks++) {
            uint32_t ah[4][4], al[4][4], bh[2][4], bl[2][4];
#pragma unroll
            for (int mi = 0; mi < 4; mi++) {
                uint32_t off = (uint32_t)(wm*64 + mi*16 + lrow) * PITCH + ks*32 + lch;
                ldm4(ah[mi], st + 0*TILEB + off);
                ldm4(al[mi], st + 1*TILEB + off);
            }
#pragma unroll
            for (int np = 0; np < 2; np++) {
                uint32_t off = (uint32_t)(wn*32 + np*16 + lrow) * PITCH + ks*32 + lch;
                ldm4(bh[np], st + 2*TILEB + off);
                ldm4(bl[np], st + 3*TILEB + off);
            }
#pragma unroll
            for (int mi = 0; mi < 4; mi++)
#pragma unroll
                for (int ni = 0; ni < 4; ni++) {
                    int np = ni >> 1, sel = ni & 1;
                    uint32_t bh0 = bh[np][sel], bh1 = bh[np][sel + 2];
                    uint32_t bl0 = bl[np][sel], bl1 = bl[np][sel + 2];
                    mma16816(acc[mi][ni], ah[mi], bh0, bh1);
                    mma16816(acc[mi][ni], ah[mi], bl0, bl1);
                    mma16816(acc[mi][ni], al[mi], bh0, bh1);
                }
        }
        __syncthreads();
    }

    // epilogue: c0,c1 -> (row, col..col+1); c2,c3 -> (row+8, ...)
    int qrow = lane >> 2, qcol = (lane & 3) * 2;
#pragma unroll
    for (int mi = 0; mi < 4; mi++) {
#pragma unroll
        for (int ni = 0; ni < 4; ni++) {
            int row = m0 + wm*64 + mi*16 + qrow;
            int col = n0 + wn*32 + ni*8 + qcol;
            float b0 = bias[col], b1 = bias[col + 1];
#pragma unroll
            for (int half = 0; half < 2; half++) {
                int r = row + half * 8;
                float v0 = acc[mi][ni][half*2 + 0] + b0;
                float v1 = acc[mi][ni][half*2 + 1] + b1;
                if (epi == 1) {
                    v0 = gelu_f(v0); v1 = gelu_f(v1);
                } else if (epi == 2) {
                    float2 rr = *(const float2*)(res + (size_t)r * N + col);
                    v0 += rr.x; v1 += rr.y;
                }
                *(float2*)(C + (size_t)r * N + col) = make_float2(v0, v1);
            }
        }
    }
}

// ---------------- helpers ----------------
__device__ __forceinline__ float block_reduce_sum(float v, float* sh) {
    int t = threadIdx.x;
    sh[t] = v; __syncthreads();
    for (int off = 128; off; off >>= 1) {
        if (t < off) sh[t] += sh[t + off];
        __syncthreads();
    }
    float r = sh[0];
    __syncthreads();
    return r;
}

// ---------------- embedding + layernorm (fused) ----------------
__global__ void embed_ln_kernel(const int* __restrict__ ids,
                                const float* __restrict__ we,
                                const float* __restrict__ pe,
                                const float* __restrict__ te,
                                const float* __restrict__ g,
                                const float* __restrict__ b) {
    __shared__ float sh[256];
    int row = blockIdx.x;
    int s = row % S_;
    int id = ids[row];
    float vals[3];
    float lsum = 0.f;
#pragma unroll
    for (int e = 0; e < 3; e++) {
        int d = threadIdx.x + e * 256;
        vals[e] = we[(size_t)id * D_ + d] + pe[(size_t)(s + 2) * D_ + d] + te[d];
        lsum += vals[e];
    }
    float mean = block_reduce_sum(lsum, sh) * (1.0f / D_);
    float lsq = 0.f;
#pragma unroll
    for (int e = 0; e < 3; e++) { float dv = vals[e] - mean; lsq += dv * dv; }
    float var = block_reduce_sum(lsq, sh) * (1.0f / D_);
    float inv = rsqrtf(var + 1e-5f);
#pragma unroll
    for (int e = 0; e < 3; e++) {
        int d = threadIdx.x + e * 256;
        g_x[(size_t)row * D_ + d] = (vals[e] - mean) * inv * g[d] + b[d];
    }
}

__global__ void ln_kernel(const float* __restrict__ in,
                          const float* __restrict__ g,
                          const float* __restrict__ b,
                          float* __restrict__ out) {
    __shared__ float sh[256];
    int row = blockIdx.x;
    const float* r = in + (size_t)row * D_;
    float vals[3];
    float lsum = 0.f;
#pragma unroll
    for (int e = 0; e < 3; e++) {
        vals[e] = r[threadIdx.x + e * 256];
        lsum += vals[e];
    }
    float mean = block_reduce_sum(lsum, sh) * (1.0f / D_);
    float lsq = 0.f;
#pragma unroll
    for (int e = 0; e < 3; e++) { float dv = vals[e] - mean; lsq += dv * dv; }
    float var = block_reduce_sum(lsq, sh) * (1.0f / D_);
    float inv = rsqrtf(var + 1e-5f);
#pragma unroll
    for (int e = 0; e < 3; e++) {
        int d = threadIdx.x + e * 256;
        out[(size_t)row * D_ + d] = (vals[e] - mean) * inv * g[d] + b[d];
    }
}

// ---------------- banded attention: warp per query, online softmax ---------
__global__ void attn_kernel(const float* __restrict__ q,
                            const float* __restrict__ k,
                            const float* __restrict__ v,
                            const float* __restrict__ mask,
                            float* __restrict__ out,
                            int half) {
    int warp = (blockIdx.x * blockDim.x + threadIdx.x) >> 5;
    int lane = threadIdx.x & 31;
    int s = warp % S_;
    int bh = warp / S_;
    int h = bh % H_;
    int b = bh / H_;

    const float* qrow = q + ((size_t)(b * S_ + s) * D_) + h * HD_;
    float2 qv = *(const float2*)(qrow + 2 * lane);
    const float scale = 0.125f;
    float q0 = qv.x * scale, q1 = qv.y * scale;

    int j0 = s - half; if (j0 < 0) j0 = 0;
    int j1 = s + half; if (j1 > S_ - 1) j1 = S_ - 1;

    float m = -1e30f, l = 0.f, acc0 = 0.f, acc1 = 0.f;
    for (int j = j0; j <= j1; j++) {
        const float* krow = k + ((size_t)(b * S_ + j) * D_) + h * HD_;
        float2 kv = *(const float2*)(krow + 2 * lane);
        float part = q0 * kv.x + q1 * kv.y;
#pragma unroll
        for (int off = 16; off; off >>= 1)
            part += __shfl_xor_sync(0xffffffffu, part, off);
        float sc = part + (1.0f - mask[b * S_ + j]) * (-1e9f);
        float mn = fmaxf(m, sc);
        float so = __expf(m - mn);
        float p = __expf(sc - mn);
        l = l * so + p;
        const float* vrow = v + ((size_t)(b * S_ + j) * D_) + h * HD_;
        float2 vv = *(const float2*)(vrow + 2 * lane);
        acc0 = acc0 * so + p * vv.x;
        acc1 = acc1 * so + p * vv.y;
        m = mn;
    }
    float inv = 1.0f / l;
    float* orow = out + ((size_t)(b * S_ + s) * D_) + h * HD_;
    orow[2 * lane]     = acc0 * inv;
    orow[2 * lane + 1] = acc1 * inv;
}

// ---------------- top head ----------------
__global__ void top_kernel(const float* __restrict__ fts,
                           const float* __restrict__ Wtop,
                           const float* __restrict__ btop,
                           float* __restrict__ out) {
    __shared__ float sh[256];
    int b = blockIdx.x;
    const float* cls = g_x + (size_t)b * S_ * D_;
    float part = 0.f;
    for (int d = threadIdx.x; d < D_; d += 256) part += cls[d] * Wtop[d];
    float r = block_reduce_sum(part, sh);
    if (threadIdx.x == 0)
        out[b] = r + fts[b] * Wtop[D_] + btop[0];
}

// ---------------- host driver ----------------
extern "C" void kernel_launch(void* const* d_in, const int* in_sizes, int n_in,
                              void* d_out, int out_size) {
    const int*   ids  = (const int*)  d_in[0];
    const float* mask = (const float*)d_in[1];
    const float* fts  = (const float*)d_in[2];
    const float* we   = (const float*)d_in[3];
    const float* pe   = (const float*)d_in[4];
    const float* te   = (const float*)d_in[5];
    const float* ln_eg= (const float*)d_in[6];
    const float* ln_eb= (const float*)d_in[7];
    const float* Wq   = (const float*)d_in[8];
    const float* bq   = (const float*)d_in[9];
    const float* Wk   = (const float*)d_in[10];
    const float* bk   = (const float*)d_in[11];
    const float* Wv   = (const float*)d_in[12];
    const float* bv   = (const float*)d_in[13];
    const float* Wo   = (const float*)d_in[14];
    const float* bo   = (const float*)d_in[15];
    const float* ln1g = (const float*)d_in[16];
    const float* ln1b = (const float*)d_in[17];
    const float* W1   = (const float*)d_in[18];
    const float* b1   = (const float*)d_in[19];
    const float* W2   = (const float*)d_in[20];
    const float* b2   = (const float*)d_in[21];
    const float* ln2g = (const float*)d_in[22];
    const float* ln2b = (const float*)d_in[23];
    const float* Wtop = (const float*)d_in[24];
    const float* btop = (const float*)d_in[25];
    float* out = (float*)d_out;

    float *x, *tt, *qp, *kp, *vp, *ap, *hp;
    cudaGetSymbolAddress((void**)&x,  g_x);
    cudaGetSymbolAddress((void**)&tt, g_t);
    cudaGetSymbolAddress((void**)&qp, g_q);
    cudaGetSymbolAddress((void**)&kp, g_k);
    cudaGetSymbolAddress((void**)&vp, g_v);
    cudaGetSymbolAddress((void**)&ap, g_a);
    cudaGetSymbolAddress((void**)&hp, g_h);

    __nv_bfloat16 *xsh,*xsl,*ash,*asl,*hsh,*hsl;
    __nv_bfloat16 *wqh,*wql,*wkh,*wkl,*wvh,*wvl,*woh,*wol,*w1h,*w1l,*w2h,*w2l;
    cudaGetSymbolAddress((void**)&xsh, g_xs_hi); cudaGetSymbolAddress((void**)&xsl, g_xs_lo);
    cudaGetSymbolAddress((void**)&ash, g_as_hi); cudaGetSymbolAddress((void**)&asl, g_as_lo);
    cudaGetSymbolAddress((void**)&hsh, g_hs_hi); cudaGetSymbolAddress((void**)&hsl, g_hs_lo);
    cudaGetSymbolAddress((void**)&wqh, g_wtq_hi); cudaGetSymbolAddress((void**)&wql, g_wtq_lo);
    cudaGetSymbolAddress((void**)&wkh, g_wtk_hi); cudaGetSymbolAddress((void**)&wkl, g_wtk_lo);
    cudaGetSymbolAddress((void**)&wvh, g_wtv_hi); cudaGetSymbolAddress((void**)&wvl, g_wtv_lo);
    cudaGetSymbolAddress((void**)&woh, g_wto_hi); cudaGetSymbolAddress((void**)&wol, g_wto_lo);
    cudaGetSymbolAddress((void**)&w1h, g_wt1_hi); cudaGetSymbolAddress((void**)&w1l, g_wt1_lo);
    cudaGetSymbolAddress((void**)&w2h, g_wt2_hi); cudaGetSymbolAddress((void**)&w2l, g_wt2_lo);

    cudaFuncSetAttribute(gemm_tc, cudaFuncAttributeMaxDynamicSharedMemorySize, GSMEM);

    static const int halves[L_] = {16,16,32,32,64,64,128,128,256,256,256,256};

    embed_ln_kernel<<<M_, 256>>>(ids, we, pe, te, ln_eg, ln_eb);

    dim3 gD(D_ / 128, M_ / 128);   // (6, 32)
    dim3 gF(FF_ / 128, M_ / 128);  // (24, 32)
    dim3 tD(D_ / 32, D_ / 32);     // weight transposes
    dim3 t1(FF_ / 32, D_ / 32);    // W1: K=768, N=3072
    dim3 t2(D_ / 32, FF_ / 32);    // W2: K=3072, N=768

    for (int i = 0; i < L_; i++) {
        const float* wq = Wq + (size_t)i * D_ * D_;
        const float* wk = Wk + (size_t)i * D_ * D_;
        const float* wv = Wv + (size_t)i * D_ * D_;
        const float* wo = Wo + (size_t)i * D_ * D_;
        const float* w1 = W1 + (size_t)i * D_ * FF_;
        const float* w2 = W2 + (size_t)i * FF_ * D_;

        // prep: split activations, transpose+split weights
        split_kernel<<<2048, 256>>>(x, xsh, xsl, M_ * D_);
        tsplit_kernel<<<tD, 256>>>(wq, wqh, wql, D_, D_);
        tsplit_kernel<<<tD, 256>>>(wk, wkh, wkl, D_, D_);
        tsplit_kernel<<<tD, 256>>>(wv, wvh, wvl, D_, D_);
        tsplit_kernel<<<tD, 256>>>(wo, woh, wol, D_, D_);
        tsplit_kernel<<<t1, 256>>>(w1, w1h, w1l, D_, FF_);
        tsplit_kernel<<<t2, 256>>>(w2, w2h, w2l, FF_, D_);

        gemm_tc<<<gD, 256, GSMEM>>>(xsh, xsl, wqh, wql, bq + (size_t)i*D_, nullptr, qp, D_, D_, 0);
        gemm_tc<<<gD, 256, GSMEM>>>(xsh, xsl, wkh, wkl, bk + (size_t)i*D_, nullptr, kp, D_, D_, 0);
        gemm_tc<<<gD, 256, GSMEM>>>(xsh, xsl, wvh, wvl, bv + (size_t)i*D_, nullptr, vp, D_, D_, 0);

        int nwarps = B_ * H_ * S_;
        attn_kernel<<<nwarps / 8, 256>>>(qp, kp, vp, mask, ap, halves[i]);

        split_kernel<<<2048, 256>>>(ap, ash, asl, M_ * D_);
        gemm_tc<<<gD, 256, GSMEM>>>(ash, asl, woh, wol, bo + (size_t)i*D_, x, tt, D_, D_, 2);
        ln_kernel<<<M_, 256>>>(tt, ln1g + (size_t)i*D_, ln1b + (size_t)i*D_, x);

        split_kernel<<<2048, 256>>>(x, xsh, xsl, M_ * D_);
        gemm_tc<<<gF, 256, GSMEM>>>(xsh, xsl, w1h, w1l, b1 + (size_t)i*FF_, nullptr, hp, FF_, D_, 1);

        split_kernel<<<4096, 256>>>(hp, hsh, hsl, M_ * FF_);
        gemm_tc<<<gD, 256, GSMEM>>>(hsh, hsl, w2h, w2l, b2 + (size_t)i*D_, x, tt, D_, FF_, 2);
        ln_kernel<<<M_, 256>>>(tt, ln2g + (size_t)i*D_, ln2b + (size_t)i*D_, x);
    }

    top_kernel<<<B_, 256>>>(fts, Wtop, btop, out);
}

// round 5
// speedup vs baseline: 3.6719x; 2.2898x over previous
#include <cuda_runtime.h>
#include <cuda_fp16.h>
#include <math.h>
#include <stdint.h>

#define B_ 2
#define S_ 2048
#define D_ 768
#define H_ 12
#define HD_ 64
#define FF_ 3072
#define L_ 12
#define M_ (B_*S_)   // 4096 rows

// ---------------- scratch (device globals; no allocation allowed) ----------
__device__ float g_x[M_*D_];
__device__ float g_t[M_*D_];
__device__ float g_q[M_*D_];
__device__ float g_k[M_*D_];
__device__ float g_v[M_*D_];

__device__ __align__(16) __half g_xh[M_*D_];    // fp16 x (GEMM A input)
__device__ __align__(16) __half g_ah[M_*D_];    // fp16 attention out
__device__ __align__(16) __half g_hh[M_*FF_];   // fp16 gelu out
// transposed fp16 weights for one layer at a time: [N][K]
__device__ __align__(16) __half g_wq[D_*D_], g_wk[D_*D_], g_wv[D_*D_], g_wo[D_*D_];
__device__ __align__(16) __half g_w1[FF_*D_];   // N=3072,K=768
__device__ __align__(16) __half g_w2[D_*FF_];   // N=768,K=3072

// ---------------- PTX helpers (base-target safe) ----------------
__device__ __forceinline__ uint32_t smem_u32(const void* p) {
    uint32_t a;
    asm("{ .reg .u64 t; cvta.to.shared.u64 t, %1; cvt.u32.u64 %0, t; }" : "=r"(a) : "l"(p));
    return a;
}
__device__ __forceinline__ void cp16(uint32_t s, const void* g) {
    asm volatile("cp.async.cg.shared.global [%0], [%1], 16;" :: "r"(s), "l"(g));
}
#define CP_COMMIT()  asm volatile("cp.async.commit_group;" ::: "memory")
#define CP_WAIT(n)   asm volatile("cp.async.wait_group %0;" :: "n"(n) : "memory")

__device__ __forceinline__ void ldm4(uint32_t* r, uint32_t addr) {
    asm volatile("ldmatrix.sync.aligned.m8n8.x4.shared.b16 {%0,%1,%2,%3}, [%4];"
        : "=r"(r[0]), "=r"(r[1]), "=r"(r[2]), "=r"(r[3]) : "r"(addr));
}
__device__ __forceinline__ void mma16816(float* c, const uint32_t* a, uint32_t b0, uint32_t b1) {
    asm volatile("mma.sync.aligned.m16n8k16.row.col.f32.f16.f16.f32 "
        "{%0,%1,%2,%3}, {%4,%5,%6,%7}, {%8,%9}, {%0,%1,%2,%3};"
        : "+f"(c[0]), "+f"(c[1]), "+f"(c[2]), "+f"(c[3])
        : "r"(a[0]), "r"(a[1]), "r"(a[2]), "r"(a[3]), "r"(b0), "r"(b1));
}

// ---------------- weight transpose: W[K][N] f32 -> T[N][K] fp16 -----------
__global__ void ttrans_kernel(const float* __restrict__ W,
                              __half* __restrict__ T, int K, int N) {
    __shared__ float t[32][33];
    int k0 = blockIdx.y * 32, n0 = blockIdx.x * 32;
    int tx = threadIdx.x & 31, ty = threadIdx.x >> 5;  // 32 x 8
#pragma unroll
    for (int i = 0; i < 4; i++)
        t[ty + i * 8][tx] = W[(size_t)(k0 + ty + i * 8) * N + n0 + tx];
    __syncthreads();
#pragma unroll
    for (int i = 0; i < 4; i++)
        T[(size_t)(n0 + ty + i * 8) * K + k0 + tx] = __float2half(t[tx][ty + i * 8]);
}

// ---------------- mma.sync fp16 GEMM ----------------
// A: [M,K] fp16 K-major. B: [N,K] fp16 K-major (pre-transposed weight).
// CTA tile 128x128, BK=32, double-buffered cp.async.
// epi: 0 none (f32 out), 1 gelu (fp16 out), 2 +residual (f32 out)
#define PITCH   80
#define TILEB   (128*PITCH)        // 10240
#define STAGE   (2*TILEB)          // 20480 (A, B)
#define GSMEM   (2*STAGE)          // 40960

__device__ __forceinline__ void load_chunk(uint32_t sbase,
                                           const __half* pA, const __half* pB,
                                           int K, int tid) {
#pragma unroll
    for (int e = 0; e < 2; e++) {
        int idx = tid + e * 256;
        int r = idx >> 2, ch = idx & 3;
        uint32_t so = r * PITCH + ch * 16;
        size_t go = (size_t)r * K + ch * 8;
        cp16(sbase + 0*TILEB + so, pA + go);
        cp16(sbase + 1*TILEB + so, pB + go);
    }
}

__device__ __forceinline__ float gelu_f(float c) {
    return 0.5f * c * (1.0f + erff(c * 0.70710678118654752f));
}

__global__ void __launch_bounds__(256)
gemm_h(const __half* __restrict__ A, const __half* __restrict__ Bt,
       const float* __restrict__ bias, const float* __restrict__ res,
       void* __restrict__ Cv, int N, int K, int epi) {
    extern __shared__ __align__(16) char smem[];
    uint32_t sb = smem_u32(smem);
    int tid = threadIdx.x, wid = tid >> 5, lane = tid & 31;
    int wm = wid >> 2, wn = wid & 3;       // warp tile: 64 rows x 32 cols
    int m0 = blockIdx.y * 128, n0 = blockIdx.x * 128;

    const __half* pA = A  + (size_t)m0 * K;
    const __half* pB = Bt + (size_t)n0 * K;

    float acc[4][4][4] = {};

    const int NC = K / 32;
    load_chunk(sb, pA, pB, K, tid);
    CP_COMMIT();

    int lrow = lane & 15;
    int lch  = (lane >> 4) * 16;

    for (int c = 0; c < NC; c++) {
        uint32_t st = sb + (c & 1) * STAGE;
        if (c + 1 < NC) {
            load_chunk(sb + ((c + 1) & 1) * STAGE, pA + (c+1)*32, pB + (c+1)*32, K, tid);
            CP_COMMIT();
            CP_WAIT(1);
        } else {
            CP_WAIT(0);
        }
        __syncthreads();

#pragma unroll
        for (int ks = 0; ks < 2; ks++) {
            uint32_t ah[4][4], bh[2][4];
#pragma unroll
            for (int mi = 0; mi < 4; mi++) {
                uint32_t off = (uint32_t)(wm*64 + mi*16 + lrow) * PITCH + ks*32 + lch;
                ldm4(ah[mi], st + 0*TILEB + off);
            }
#pragma unroll
            for (int np = 0; np < 2; np++) {
                uint32_t off = (uint32_t)(wn*32 + np*16 + lrow) * PITCH + ks*32 + lch;
                ldm4(bh[np], st + 1*TILEB + off);
            }
#pragma unroll
            for (int mi = 0; mi < 4; mi++)
#pragma unroll
                for (int ni = 0; ni < 4; ni++) {
                    int np = ni >> 1, sel = ni & 1;
                    mma16816(acc[mi][ni], ah[mi], bh[np][sel], bh[np][sel + 2]);
                }
        }
        __syncthreads();
    }

    int qrow = lane >> 2, qcol = (lane & 3) * 2;
#pragma unroll
    for (int mi = 0; mi < 4; mi++) {
#pragma unroll
        for (int ni = 0; ni < 4; ni++) {
            int row = m0 + wm*64 + mi*16 + qrow;
            int col = n0 + wn*32 + ni*8 + qcol;
            float b0 = bias[col], b1 = bias[col + 1];
#pragma unroll
            for (int half = 0; half < 2; half++) {
                int r = row + half * 8;
                float v0 = acc[mi][ni][half*2 + 0] + b0;
                float v1 = acc[mi][ni][half*2 + 1] + b1;
                if (epi == 1) {
                    v0 = gelu_f(v0); v1 = gelu_f(v1);
                    *(__half2*)((__half*)Cv + (size_t)r * N + col) =
                        __floats2half2_rn(v0, v1);
                } else {
                    if (epi == 2) {
                        float2 rr = *(const float2*)(res + (size_t)r * N + col);
                        v0 += rr.x; v1 += rr.y;
                    }
                    *(float2*)((float*)Cv + (size_t)r * N + col) = make_float2(v0, v1);
                }
            }
        }
    }
}

// ---------------- helpers ----------------
__device__ __forceinline__ float block_reduce_sum(float v, float* sh) {
    int t = threadIdx.x;
    sh[t] = v; __syncthreads();
    for (int off = 128; off; off >>= 1) {
        if (t < off) sh[t] += sh[t + off];
        __syncthreads();
    }
    float r = sh[0];
    __syncthreads();
    return r;
}
__device__ __forceinline__ float warp_max(float v) {
#pragma unroll
    for (int o = 16; o; o >>= 1) v = fmaxf(v, __shfl_xor_sync(0xffffffffu, v, o));
    return v;
}
__device__ __forceinline__ float warp_sum(float v) {
#pragma unroll
    for (int o = 16; o; o >>= 1) v += __shfl_xor_sync(0xffffffffu, v, o);
    return v;
}

// ---------------- embedding + layernorm (fused, writes f32 + fp16) --------
__global__ void embed_ln_kernel(const int* __restrict__ ids,
                                const float* __restrict__ we,
                                const float* __restrict__ pe,
                                const float* __restrict__ te,
                                const float* __restrict__ g,
                                const float* __restrict__ b) {
    __shared__ float sh[256];
    int row = blockIdx.x;
    int s = row % S_;
    int id = ids[row];
    float vals[3];
    float lsum = 0.f;
#pragma unroll
    for (int e = 0; e < 3; e++) {
        int d = threadIdx.x + e * 256;
        vals[e] = we[(size_t)id * D_ + d] + pe[(size_t)(s + 2) * D_ + d] + te[d];
        lsum += vals[e];
    }
    float mean = block_reduce_sum(lsum, sh) * (1.0f / D_);
    float lsq = 0.f;
#pragma unroll
    for (int e = 0; e < 3; e++) { float dv = vals[e] - mean; lsq += dv * dv; }
    float var = block_reduce_sum(lsq, sh) * (1.0f / D_);
    float inv = rsqrtf(var + 1e-5f);
#pragma unroll
    for (int e = 0; e < 3; e++) {
        int d = threadIdx.x + e * 256;
        float r = (vals[e] - mean) * inv * g[d] + b[d];
        g_x[(size_t)row * D_ + d] = r;
        g_xh[(size_t)row * D_ + d] = __float2half(r);
    }
}

__global__ void ln_kernel(const float* __restrict__ in,
                          const float* __restrict__ g,
                          const float* __restrict__ b,
                          float* __restrict__ out,
                          __half* __restrict__ outh) {
    __shared__ float sh[256];
    int row = blockIdx.x;
    const float* r = in + (size_t)row * D_;
    float vals[3];
    float lsum = 0.f;
#pragma unroll
    for (int e = 0; e < 3; e++) {
        vals[e] = r[threadIdx.x + e * 256];
        lsum += vals[e];
    }
    float mean = block_reduce_sum(lsum, sh) * (1.0f / D_);
    float lsq = 0.f;
#pragma unroll
    for (int e = 0; e < 3; e++) { float dv = vals[e] - mean; lsq += dv * dv; }
    float var = block_reduce_sum(lsq, sh) * (1.0f / D_);
    float inv = rsqrtf(var + 1e-5f);
#pragma unroll
    for (int e = 0; e < 3; e++) {
        int d = threadIdx.x + e * 256;
        float rr = (vals[e] - mean) * inv * g[d] + b[d];
        out[(size_t)row * D_ + d] = rr;
        outh[(size_t)row * D_ + d] = __float2half(rr);
    }
}

// ---------------- tiled banded attention ----------------
// block = (query tile of 32, b*h). 256 threads = 8 warps, warp -> 4 queries.
// Scores: lane = key (K tile in SMEM). PV: shfl-broadcast p, lane = dim pair.
__global__ void __launch_bounds__(256)
attn_tile(const float* __restrict__ q, const float* __restrict__ k,
          const float* __restrict__ v, const float* __restrict__ mask,
          __half* __restrict__ outh, int half) {
    __shared__ float qs[32][64];
    __shared__ float ks[32][65];
    __shared__ float vs[32][64];
    int tid = threadIdx.x, wid = tid >> 5, lane = tid & 31;
    int qt = blockIdx.x * 32;
    int bh = blockIdx.y;
    int b = bh / H_, h = bh % H_;
    const size_t base = (size_t)b * S_;

#pragma unroll
    for (int i = 0; i < 8; i++) {
        int idx = tid + i * 256;
        int r = idx >> 6, d = idx & 63;
        qs[r][d] = q[(base + qt + r) * D_ + h * HD_ + d] * 0.125f;
    }

    int q0 = wid * 4;
    float m[4], l[4], o0[4], o1[4];
#pragma unroll
    for (int i = 0; i < 4; i++) { m[i] = -1e30f; l[i] = 0.f; o0[i] = 0.f; o1[i] = 0.f; }

    int kt0 = (qt - half) >> 5; if (kt0 < 0) kt0 = 0;
    int kt1 = (qt + 31 + half) >> 5; if (kt1 > S_/32 - 1) kt1 = S_/32 - 1;

    for (int kt = kt0; kt <= kt1; kt++) {
        __syncthreads();
        int j0 = kt * 32;
#pragma unroll
        for (int i = 0; i < 8; i++) {
            int idx = tid + i * 256;
            int r = idx >> 6, d = idx & 63;
            ks[r][d] = k[(base + j0 + r) * D_ + h * HD_ + d];
            vs[r][d] = v[(base + j0 + r) * D_ + h * HD_ + d];
        }
        __syncthreads();

        int j = j0 + lane;
        float ka = (1.0f - mask[base + j]) * -1e9f;
        float sc[4] = {0.f, 0.f, 0.f, 0.f};
#pragma unroll
        for (int d = 0; d < 64; d++) {
            float kv = ks[lane][d];
            sc[0] += qs[q0 + 0][d] * kv;
            sc[1] += qs[q0 + 1][d] * kv;
            sc[2] += qs[q0 + 2][d] * kv;
            sc[3] += qs[q0 + 3][d] * kv;
        }
#pragma unroll
        for (int i = 0; i < 4; i++) {
            int qg = qt + q0 + i;
            bool valid = (j >= qg - half) && (j <= qg + half);
            float s = valid ? sc[i] + ka : -1e9f;
            float tmax = warp_max(s);
            float mn = fmaxf(m[i], tmax);
            float scale = __expf(m[i] - mn);
            float p = __expf(s - mn);
            float ls = warp_sum(p);
            m[i] = mn;
            l[i] = l[i] * scale + ls;
            o0[i] *= scale; o1[i] *= scale;
            if (ls != 0.f) {
#pragma unroll 8
                for (int kk = 0; kk < 32; kk++) {
                    float pk = __shfl_sync(0xffffffffu, p, kk);
                    float2 vv = ((const float2*)vs[kk])[lane];
                    o0[i] += pk * vv.x;
                    o1[i] += pk * vv.y;
                }
            }
        }
    }

#pragma unroll
    for (int i = 0; i < 4; i++) {
        int qg = qt + q0 + i;
        float inv = 1.0f / l[i];
        *(__half2*)(outh + (base + qg) * D_ + h * HD_ + 2 * lane) =
            __floats2half2_rn(o0[i] * inv, o1[i] * inv);
    }
}

// ---------------- top head ----------------
__global__ void top_kernel(const float* __restrict__ fts,
                           const float* __restrict__ Wtop,
                           const float* __restrict__ btop,
                           float* __restrict__ out) {
    __shared__ float sh[256];
    int b = blockIdx.x;
    const float* cls = g_x + (size_t)b * S_ * D_;
    float part = 0.f;
    for (int d = threadIdx.x; d < D_; d += 256) part += cls[d] * Wtop[d];
    float r = block_reduce_sum(part, sh);
    if (threadIdx.x == 0)
        out[b] = r + fts[b] * Wtop[D_] + btop[0];
}

// ---------------- host driver ----------------
extern "C" void kernel_launch(void* const* d_in, const int* in_sizes, int n_in,
                              void* d_out, int out_size) {
    const int*   ids  = (const int*)  d_in[0];
    const float* mask = (const float*)d_in[1];
    const float* fts  = (const float*)d_in[2];
    const float* we   = (const float*)d_in[3];
    const float* pe   = (const float*)d_in[4];
    const float* te   = (const float*)d_in[5];
    const float* ln_eg= (const float*)d_in[6];
    const float* ln_eb= (const float*)d_in[7];
    const float* Wq   = (const float*)d_in[8];
    const float* bq   = (const float*)d_in[9];
    const float* Wk   = (const float*)d_in[10];
    const float* bk   = (const float*)d_in[11];
    const float* Wv   = (const float*)d_in[12];
    const float* bv   = (const float*)d_in[13];
    const float* Wo   = (const float*)d_in[14];
    const float* bo   = (const float*)d_in[15];
    const float* ln1g = (const float*)d_in[16];
    const float* ln1b = (const float*)d_in[17];
    const float* W1   = (const float*)d_in[18];
    const float* b1   = (const float*)d_in[19];
    const float* W2   = (const float*)d_in[20];
    const float* b2   = (const float*)d_in[21];
    const float* ln2g = (const float*)d_in[22];
    const float* ln2b = (const float*)d_in[23];
    const float* Wtop = (const float*)d_in[24];
    const float* btop = (const float*)d_in[25];
    float* out = (float*)d_out;

    float *x, *tt, *qp, *kp, *vp;
    cudaGetSymbolAddress((void**)&x,  g_x);
    cudaGetSymbolAddress((void**)&tt, g_t);
    cudaGetSymbolAddress((void**)&qp, g_q);
    cudaGetSymbolAddress((void**)&kp, g_k);
    cudaGetSymbolAddress((void**)&vp, g_v);

    __half *xh, *ah, *hh, *wq, *wk, *wv, *wo, *w1, *w2;
    cudaGetSymbolAddress((void**)&xh, g_xh);
    cudaGetSymbolAddress((void**)&ah, g_ah);
    cudaGetSymbolAddress((void**)&hh, g_hh);
    cudaGetSymbolAddress((void**)&wq, g_wq);
    cudaGetSymbolAddress((void**)&wk, g_wk);
    cudaGetSymbolAddress((void**)&wv, g_wv);
    cudaGetSymbolAddress((void**)&wo, g_wo);
    cudaGetSymbolAddress((void**)&w1, g_w1);
    cudaGetSymbolAddress((void**)&w2, g_w2);

    cudaFuncSetAttribute(gemm_h, cudaFuncAttributeMaxDynamicSharedMemorySize, GSMEM);

    static const int halves[L_] = {16,16,32,32,64,64,128,128,256,256,256,256};

    embed_ln_kernel<<<M_, 256>>>(ids, we, pe, te, ln_eg, ln_eb);

    dim3 gD(D_ / 128, M_ / 128);   // (6, 32)
    dim3 gF(FF_ / 128, M_ / 128);  // (24, 32)
    dim3 tD(D_ / 32, D_ / 32);
    dim3 t1(FF_ / 32, D_ / 32);    // W1: K=768, N=3072
    dim3 t2(D_ / 32, FF_ / 32);    // W2: K=3072, N=768
    dim3 ga(S_ / 32, B_ * H_);     // (64, 24)

    for (int i = 0; i < L_; i++) {
        const float* pwq = Wq + (size_t)i * D_ * D_;
        const float* pwk = Wk + (size_t)i * D_ * D_;
        const float* pwv = Wv + (size_t)i * D_ * D_;
        const float* pwo = Wo + (size_t)i * D_ * D_;
        const float* pw1 = W1 + (size_t)i * D_ * FF_;
        const float* pw2 = W2 + (size_t)i * FF_ * D_;

        ttrans_kernel<<<tD, 256>>>(pwq, wq, D_, D_);
        ttrans_kernel<<<tD, 256>>>(pwk, wk, D_, D_);
        ttrans_kernel<<<tD, 256>>>(pwv, wv, D_, D_);
        ttrans_kernel<<<tD, 256>>>(pwo, wo, D_, D_);
        ttrans_kernel<<<t1, 256>>>(pw1, w1, D_, FF_);
        ttrans_kernel<<<t2, 256>>>(pw2, w2, FF_, D_);

        gemm_h<<<gD, 256, GSMEM>>>(xh, wq, bq + (size_t)i*D_, nullptr, qp, D_, D_, 0);
        gemm_h<<<gD, 256, GSMEM>>>(xh, wk, bk + (size_t)i*D_, nullptr, kp, D_, D_, 0);
        gemm_h<<<gD, 256, GSMEM>>>(xh, wv, bv + (size_t)i*D_, nullptr, vp, D_, D_, 0);

        attn_tile<<<ga, 256>>>(qp, kp, vp, mask, ah, halves[i]);

        gemm_h<<<gD, 256, GSMEM>>>(ah, wo, bo + (size_t)i*D_, x, tt, D_, D_, 2);
        ln_kernel<<<M_, 256>>>(tt, ln1g + (size_t)i*D_, ln1b + (size_t)i*D_, x, xh);

        gemm_h<<<gF, 256, GSMEM>>>(xh, w1, b1 + (size_t)i*FF_, nullptr, hh, FF_, D_, 1);

        gemm_h<<<gD, 256, GSMEM>>>(hh, w2, b2 + (size_t)i*D_, x, tt, D_, FF_, 2);
        ln_kernel<<<M_, 256>>>(tt, ln2g + (size_t)i*D_, ln2b + (size_t)i*D_, x, xh);
    }

    top_kernel<<<B_, 256>>>(fts, Wtop, btop, out);
}

// round 7
// speedup vs baseline: 3.8987x; 1.0618x over previous
#include <cuda_runtime.h>
#include <cuda_fp16.h>
#include <math.h>
#include <stdint.h>

#define B_ 2
#define S_ 2048
#define D_ 768
#define H_ 12
#define HD_ 64
#define FF_ 3072
#define L_ 12
#define M_ (B_*S_)   // 4096 rows

// ---------------- scratch (device globals; no allocation allowed) ----------
__device__ float g_x[M_*D_];
__device__ float g_t[M_*D_];

__device__ __align__(16) __half g_xh[M_*D_];    // fp16 x (GEMM A input)
__device__ __align__(16) __half g_ah[M_*D_];    // fp16 attention out
__device__ __align__(16) __half g_hh[M_*FF_];   // fp16 gelu out
__device__ __align__(16) __half g_qh[M_*D_], g_kh[M_*D_], g_vh[M_*D_];
// transposed fp16 weights, ALL layers: [L][N][K]
__device__ __align__(16) __half g_wq[L_*D_*D_], g_wk[L_*D_*D_], g_wv[L_*D_*D_], g_wo[L_*D_*D_];
__device__ __align__(16) __half g_w1[L_*FF_*D_];   // N=3072,K=768
__device__ __align__(16) __half g_w2[L_*D_*FF_];   // N=768,K=3072

// ---------------- PTX helpers (base-target safe) ----------------
__device__ __forceinline__ uint32_t smem_u32(const void* p) {
    uint32_t a;
    asm("{ .reg .u64 t; cvta.to.shared.u64 t, %1; cvt.u32.u64 %0, t; }" : "=r"(a) : "l"(p));
    return a;
}
__device__ __forceinline__ void cp16(uint32_t s, const void* g) {
    asm volatile("cp.async.cg.shared.global [%0], [%1], 16;" :: "r"(s), "l"(g));
}
#define CP_COMMIT()  asm volatile("cp.async.commit_group;" ::: "memory")
#define CP_WAIT(n)   asm volatile("cp.async.wait_group %0;" :: "n"(n) : "memory")

__device__ __forceinline__ void ldm4(uint32_t* r, uint32_t addr) {
    asm volatile("ldmatrix.sync.aligned.m8n8.x4.shared.b16 {%0,%1,%2,%3}, [%4];"
        : "=r"(r[0]), "=r"(r[1]), "=r"(r[2]), "=r"(r[3]) : "r"(addr));
}
__device__ __forceinline__ void mma16816(float* c, const uint32_t* a, uint32_t b0, uint32_t b1) {
    asm volatile("mma.sync.aligned.m16n8k16.row.col.f32.f16.f16.f32 "
        "{%0,%1,%2,%3}, {%4,%5,%6,%7}, {%8,%9}, {%0,%1,%2,%3};"
        : "+f"(c[0]), "+f"(c[1]), "+f"(c[2]), "+f"(c[3])
        : "r"(a[0]), "r"(a[1]), "r"(a[2]), "r"(a[3]), "r"(b0), "r"(b1));
}

// ---------------- batched weight transpose: W[L][K][N] f32 -> T[L][N][K] fp16
__global__ void ttrans_all(const float* __restrict__ W,
                           __half* __restrict__ T, int K, int N) {
    __shared__ float t[32][33];
    int li = blockIdx.z;
    const float* Wl = W + (size_t)li * K * N;
    __half* Tl = T + (size_t)li * K * N;
    int k0 = blockIdx.y * 32, n0 = blockIdx.x * 32;
    int tx = threadIdx.x & 31, ty = threadIdx.x >> 5;  // 32 x 8
#pragma unroll
    for (int i = 0; i < 4; i++)
        t[ty + i * 8][tx] = Wl[(size_t)(k0 + ty + i * 8) * N + n0 + tx];
    __syncthreads();
#pragma unroll
    for (int i = 0; i < 4; i++)
        Tl[(size_t)(n0 + ty + i * 8) * K + k0 + tx] = __float2half(t[tx][ty + i * 8]);
}

// ---------------- mma.sync fp16 GEMM ----------------
// A: [M,K] fp16 K-major. B: [N,K] fp16 K-major.
// CTA tile 256x128, 8 warps (4x2), warp tile 64x64, BK=32, double-buffered.
// epi: 0 none (f32), 1 gelu (fp16), 2 +residual (f32), 3 bias-only (fp16)
#define PITCH   80
#define TA      (256*PITCH)        // 20480
#define TB      (128*PITCH)        // 10240
#define STAGE   (TA+TB)            // 30720
#define GSMEM   (2*STAGE)          // 61440

__device__ __forceinline__ void load_chunk(uint32_t sbase,
                                           const __half* pA, const __half* pB,
                                           int K, int tid) {
#pragma unroll
    for (int e = 0; e < 4; e++) {       // A: 256 rows x 4 chunks = 1024
        int idx = tid + e * 256;
        int r = idx >> 2, ch = idx & 3;
        cp16(sbase + r * PITCH + ch * 16, pA + (size_t)r * K + ch * 8);
    }
#pragma unroll
    for (int e = 0; e < 2; e++) {       // B: 128 rows x 4 chunks = 512
        int idx = tid + e * 256;
        int r = idx >> 2, ch = idx & 3;
        cp16(sbase + TA + r * PITCH + ch * 16, pB + (size_t)r * K + ch * 8);
    }
}

__device__ __forceinline__ float gelu_f(float c) {
    return 0.5f * c * (1.0f + erff(c * 0.70710678118654752f));
}

__global__ void __launch_bounds__(256, 1)
gemm_h(const __half* __restrict__ A, const __half* __restrict__ Bt,
       const float* __restrict__ bias, const float* __restrict__ res,
       void* __restrict__ Cv, int N, int K, int epi) {
    extern __shared__ __align__(16) char smem[];
    uint32_t sb = smem_u32(smem);
    int tid = threadIdx.x, wid = tid >> 5, lane = tid & 31;
    int wm = wid >> 1, wn = wid & 1;       // warp tile: 64 rows x 64 cols
    int m0 = blockIdx.y * 256, n0 = blockIdx.x * 128;

    const __half* pA = A  + (size_t)m0 * K;
    const __half* pB = Bt + (size_t)n0 * K;

    float acc[4][8][4] = {};

    const int NC = K / 32;
    load_chunk(sb, pA, pB, K, tid);
    CP_COMMIT();

    int lrow = lane & 15;
    int lch  = (lane >> 4) * 16;

    for (int c = 0; c < NC; c++) {
        uint32_t st = sb + (c & 1) * STAGE;
        if (c + 1 < NC) {
            load_chunk(sb + ((c + 1) & 1) * STAGE, pA + (c+1)*32, pB + (c+1)*32, K, tid);
            CP_COMMIT();
            CP_WAIT(1);
        } else {
            CP_WAIT(0);
        }
        __syncthreads();

#pragma unroll
        for (int ks = 0; ks < 2; ks++) {
            uint32_t ah[4][4], bh[4][4];
#pragma unroll
            for (int mi = 0; mi < 4; mi++) {
                uint32_t off = (uint32_t)(wm*64 + mi*16 + lrow) * PITCH + ks*32 + lch;
                ldm4(ah[mi], st + off);
            }
#pragma unroll
            for (int np = 0; np < 4; np++) {
                uint32_t off = (uint32_t)(wn*64 + np*16 + lrow) * PITCH + ks*32 + lch;
                ldm4(bh[np], st + TA + off);
            }
#pragma unroll
            for (int mi = 0; mi < 4; mi++)
#pragma unroll
                for (int ni = 0; ni < 8; ni++) {
                    int np = ni >> 1, sel = ni & 1;
                    mma16816(acc[mi][ni], ah[mi], bh[np][sel], bh[np][sel + 2]);
                }
        }
        __syncthreads();
    }

    int qrow = lane >> 2, qcol = (lane & 3) * 2;
#pragma unroll
    for (int mi = 0; mi < 4; mi++) {
#pragma unroll
        for (int ni = 0; ni < 8; ni++) {
            int row = m0 + wm*64 + mi*16 + qrow;
            int col = n0 + wn*64 + ni*8 + qcol;
            float b0 = bias[col], b1 = bias[col + 1];
#pragma unroll
            for (int hh = 0; hh < 2; hh++) {
                int r = row + hh * 8;
                float v0 = acc[mi][ni][hh*2 + 0] + b0;
                float v1 = acc[mi][ni][hh*2 + 1] + b1;
                if (epi == 1) {
                    v0 = gelu_f(v0); v1 = gelu_f(v1);
                    *(__half2*)((__half*)Cv + (size_t)r * N + col) = __floats2half2_rn(v0, v1);
                } else if (epi == 3) {
                    *(__half2*)((__half*)Cv + (size_t)r * N + col) = __floats2half2_rn(v0, v1);
                } else {
                    if (epi == 2) {
                        float2 rr = *(const float2*)(res + (size_t)r * N + col);
                        v0 += rr.x; v1 += rr.y;
                    }
                    *(float2*)((float*)Cv + (size_t)r * N + col) = make_float2(v0, v1);
                }
            }
        }
    }
}

// ---------------- reductions ----------------
__device__ __forceinline__ float warp_max(float v) {
#pragma unroll
    for (int o = 16; o; o >>= 1) v = fmaxf(v, __shfl_xor_sync(0xffffffffu, v, o));
    return v;
}
__device__ __forceinline__ float warp_sum(float v) {
#pragma unroll
    for (int o = 16; o; o >>= 1) v += __shfl_xor_sync(0xffffffffu, v, o);
    return v;
}
// block-wide sum of (a, b) over 256 threads; 2 syncthreads total
__device__ __forceinline__ float2 block_sum2(float a, float b) {
    __shared__ float sa[8], sb2[8];
    int wid = threadIdx.x >> 5, lane = threadIdx.x & 31;
    a = warp_sum(a); b = warp_sum(b);
    if (lane == 0) { sa[wid] = a; sb2[wid] = b; }
    __syncthreads();
    float ra = sa[lane & 7], rb = sb2[lane & 7];
#pragma unroll
    for (int o = 4; o; o >>= 1) {
        ra += __shfl_xor_sync(0xffffffffu, ra, o);
        rb += __shfl_xor_sync(0xffffffffu, rb, o);
    }
    // every lane in each warp now has the total (lanes 8-31 mirror 0-7 pattern)
    ra = __shfl_sync(0xffffffffu, ra, 0);
    rb = __shfl_sync(0xffffffffu, rb, 0);
    __syncthreads();
    return make_float2(ra, rb);
}

// ---------------- embedding + layernorm ----------------
__global__ void embed_ln_kernel(const int* __restrict__ ids,
                                const float* __restrict__ we,
                                const float* __restrict__ pe,
                                const float* __restrict__ te,
                                const float* __restrict__ g,
                                const float* __restrict__ b) {
    int row = blockIdx.x;
    int s = row % S_;
    int id = ids[row];
    float vals[3];
    float lsum = 0.f, lsq = 0.f;
#pragma unroll
    for (int e = 0; e < 3; e++) {
        int d = threadIdx.x + e * 256;
        vals[e] = we[(size_t)id * D_ + d] + pe[(size_t)(s + 2) * D_ + d] + te[d];
        lsum += vals[e]; lsq += vals[e] * vals[e];
    }
    float2 t = block_sum2(lsum, lsq);
    float mean = t.x * (1.0f / D_);
    float var = t.y * (1.0f / D_) - mean * mean;
    float inv = rsqrtf(var + 1e-5f);
#pragma unroll
    for (int e = 0; e < 3; e++) {
        int d = threadIdx.x + e * 256;
        float r = (vals[e] - mean) * inv * g[d] + b[d];
        g_x[(size_t)row * D_ + d] = r;
        g_xh[(size_t)row * D_ + d] = __float2half(r);
    }
}

__global__ void ln_kernel(const float* __restrict__ in,
                          const float* __restrict__ g,
                          const float* __restrict__ b,
                          float* __restrict__ out,
                          __half* __restrict__ outh) {
    int row = blockIdx.x;
    const float* r = in + (size_t)row * D_;
    float vals[3];
    float lsum = 0.f, lsq = 0.f;
#pragma unroll
    for (int e = 0; e < 3; e++) {
        vals[e] = r[threadIdx.x + e * 256];
        lsum += vals[e]; lsq += vals[e] * vals[e];
    }
    float2 t = block_sum2(lsum, lsq);
    float mean = t.x * (1.0f / D_);
    float var = t.y * (1.0f / D_) - mean * mean;
    float inv = rsqrtf(var + 1e-5f);
#pragma unroll
    for (int e = 0; e < 3; e++) {
        int d = threadIdx.x + e * 256;
        float rr = (vals[e] - mean) * inv * g[d] + b[d];
        out[(size_t)row * D_ + d] = rr;
        outh[(size_t)row * D_ + d] = __float2half(rr);
    }
}

// ---------------- tiled banded attention (fp16 in/out, f32 math) ----------
__global__ void __launch_bounds__(256)
attn_tile(const __half* __restrict__ q, const __half* __restrict__ k,
          const __half* __restrict__ v, const float* __restrict__ mask,
          __half* __restrict__ outh, int half) {
    __shared__ float qs[32][64];
    __shared__ float ks[32][65];
    __shared__ float vs[32][64];
    int tid = threadIdx.x, wid = tid >> 5, lane = tid & 31;
    int qt = blockIdx.x * 32;
    int bh = blockIdx.y;
    int b = bh / H_, h = bh % H_;
    const size_t base = (size_t)b * S_;

#pragma unroll
    for (int i = 0; i < 4; i++) {
        int idx = tid + i * 256;
        int r = idx >> 5, dp = idx & 31;
        float2 f = __half22float2(*(const __half2*)(q + (base + qt + r) * D_ + h * HD_ + 2 * dp));
        qs[r][2*dp] = f.x * 0.125f; qs[r][2*dp+1] = f.y * 0.125f;
    }

    int q0 = wid * 4;
    float m[4], l[4], o0[4], o1[4];
#pragma unroll
    for (int i = 0; i < 4; i++) { m[i] = -1e30f; l[i] = 0.f; o0[i] = 0.f; o1[i] = 0.f; }

    int kt0 = (qt - half) >> 5; if (kt0 < 0) kt0 = 0;
    int kt1 = (qt + 31 + half) >> 5; if (kt1 > S_/32 - 1) kt1 = S_/32 - 1;

    for (int kt = kt0; kt <= kt1; kt++) {
        __syncthreads();
        int j0 = kt * 32;
#pragma unroll
        for (int i = 0; i < 4; i++) {
            int idx = tid + i * 256;
            int r = idx >> 5, dp = idx & 31;
            float2 fk = __half22float2(*(const __half2*)(k + (base + j0 + r) * D_ + h * HD_ + 2 * dp));
            float2 fv = __half22float2(*(const __half2*)(v + (base + j0 + r) * D_ + h * HD_ + 2 * dp));
            ks[r][2*dp] = fk.x; ks[r][2*dp+1] = fk.y;
            vs[r][2*dp] = fv.x; vs[r][2*dp+1] = fv.y;
        }
        __syncthreads();

        int j = j0 + lane;
        float ka = (1.0f - mask[base + j]) * -1e9f;
        float sc[4] = {0.f, 0.f, 0.f, 0.f};
#pragma unroll
        for (int d = 0; d < 64; d++) {
            float kv = ks[lane][d];
            sc[0] += qs[q0 + 0][d] * kv;
            sc[1] += qs[q0 + 1][d] * kv;
            sc[2] += qs[q0 + 2][d] * kv;
            sc[3] += qs[q0 + 3][d] * kv;
        }
#pragma unroll
        for (int i = 0; i < 4; i++) {
            int qg = qt + q0 + i;
            bool valid = (j >= qg - half) && (j <= qg + half);
            float s = valid ? sc[i] + ka : -1e9f;
            float tmax = warp_max(s);
            float mn = fmaxf(m[i], tmax);
            float scale = __expf(m[i] - mn);
            float p = __expf(s - mn);
            float ls = warp_sum(p);
            m[i] = mn;
            l[i] = l[i] * scale + ls;
            o0[i] *= scale; o1[i] *= scale;
            if (ls != 0.f) {
#pragma unroll 8
                for (int kk = 0; kk < 32; kk++) {
                    float pk = __shfl_sync(0xffffffffu, p, kk);
                    float2 vv = ((const float2*)vs[kk])[lane];
                    o0[i] += pk * vv.x;
                    o1[i] += pk * vv.y;
                }
            }
        }
    }

#pragma unroll
    for (int i = 0; i < 4; i++) {
        int qg = qt + q0 + i;
        float inv = 1.0f / l[i];
        *(__half2*)(outh + (base + qg) * D_ + h * HD_ + 2 * lane) =
            __floats2half2_rn(o0[i] * inv, o1[i] * inv);
    }
}

// ---------------- top head ----------------
__global__ void top_kernel(const float* __restrict__ fts,
                           const float* __restrict__ Wtop,
                           const float* __restrict__ btop,
                           float* __restrict__ out) {
    int b = blockIdx.x;
    const float* cls = g_x + (size_t)b * S_ * D_;
    float part = 0.f;
    for (int d = threadIdx.x; d < D_; d += 256) part += cls[d] * Wtop[d];
    float2 t = block_sum2(part, 0.f);
    if (threadIdx.x == 0)
        out[b] = t.x + fts[b] * Wtop[D_] + btop[0];
}

// ---------------- host driver ----------------
extern "C" void kernel_launch(void* const* d_in, const int* in_sizes, int n_in,
                              void* d_out, int out_size) {
    const int*   ids  = (const int*)  d_in[0];
    const float* mask = (const float*)d_in[1];
    const float* fts  = (const float*)d_in[2];
    const float* we   = (const float*)d_in[3];
    const float* pe   = (const float*)d_in[4];
    const float* te   = (const float*)d_in[5];
    const float* ln_eg= (const float*)d_in[6];
    const float* ln_eb= (const float*)d_in[7];
    const float* Wq   = (const float*)d_in[8];
    const float* bq   = (const float*)d_in[9];
    const float* Wk   = (const float*)d_in[10];
    const float* bk   = (const float*)d_in[11];
    const float* Wv   = (const float*)d_in[12];
    const float* bv   = (const float*)d_in[13];
    const float* Wo   = (const float*)d_in[14];
    const float* bo   = (const float*)d_in[15];
    const float* ln1g = (const float*)d_in[16];
    const float* ln1b = (const float*)d_in[17];
    const float* W1   = (const float*)d_in[18];
    const float* b1   = (const float*)d_in[19];
    const float* W2   = (const float*)d_in[20];
    const float* b2   = (const float*)d_in[21];
    const float* ln2g = (const float*)d_in[22];
    const float* ln2b = (const float*)d_in[23];
    const float* Wtop = (const float*)d_in[24];
    const float* btop = (const float*)d_in[25];
    float* out = (float*)d_out;

    float *x, *tt;
    cudaGetSymbolAddress((void**)&x,  g_x);
    cudaGetSymbolAddress((void**)&tt, g_t);

    __half *xh, *ah, *hh, *qh, *kh, *vh, *wq, *wk, *wv, *wo, *w1, *w2;
    cudaGetSymbolAddress((void**)&xh, g_xh);
    cudaGetSymbolAddress((void**)&ah, g_ah);
    cudaGetSymbolAddress((void**)&hh, g_hh);
    cudaGetSymbolAddress((void**)&qh, g_qh);
    cudaGetSymbolAddress((void**)&kh, g_kh);
    cudaGetSymbolAddress((void**)&vh, g_vh);
    cudaGetSymbolAddress((void**)&wq, g_wq);
    cudaGetSymbolAddress((void**)&wk, g_wk);
    cudaGetSymbolAddress((void**)&wv, g_wv);
    cudaGetSymbolAddress((void**)&wo, g_wo);
    cudaGetSymbolAddress((void**)&w1, g_w1);
    cudaGetSymbolAddress((void**)&w2, g_w2);

    cudaFuncSetAttribute(gemm_h, cudaFuncAttributeMaxDynamicSharedMemorySize, GSMEM);

    static const int halves[L_] = {16,16,32,32,64,64,128,128,256,256,256,256};

    embed_ln_kernel<<<M_, 256>>>(ids, we, pe, te, ln_eg, ln_eb);

    // all weight transposes up-front (batched over layers)
    dim3 tD(D_ / 32, D_ / 32, L_);
    dim3 t1(FF_ / 32, D_ / 32, L_);
    dim3 t2(D_ / 32, FF_ / 32, L_);
    ttrans_all<<<tD, 256>>>(Wq, wq, D_, D_);
    ttrans_all<<<tD, 256>>>(Wk, wk, D_, D_);
    ttrans_all<<<tD, 256>>>(Wv, wv, D_, D_);
    ttrans_all<<<tD, 256>>>(Wo, wo, D_, D_);
    ttrans_all<<<t1, 256>>>(W1, w1, D_, FF_);
    ttrans_all<<<t2, 256>>>(W2, w2, FF_, D_);

    dim3 gD(D_ / 128, M_ / 256);   // (6, 16)
    dim3 gF(FF_ / 128, M_ / 256);  // (24, 16)
    dim3 ga(S_ / 32, B_ * H_);     // (64, 24)

    for (int i = 0; i < L_; i++) {
        __half* lwq = wq + (size_t)i * D_ * D_;
        __half* lwk = wk + (size_t)i * D_ * D_;
        __half* lwv = wv + (size_t)i * D_ * D_;
        __half* lwo = wo + (size_t)i * D_ * D_;
        __half* lw1 = w1 + (size_t)i * FF_ * D_;
        __half* lw2 = w2 + (size_t)i * D_ * FF_;

        gemm_h<<<gD, 256, GSMEM>>>(xh, lwq, bq + (size_t)i*D_, nullptr, qh, D_, D_, 3);
        gemm_h<<<gD, 256, GSMEM>>>(xh, lwk, bk + (size_t)i*D_, nullptr, kh, D_, D_, 3);
        gemm_h<<<gD, 256, GSMEM>>>(xh, lwv, bv + (size_t)i*D_, nullptr, vh, D_, D_, 3);

        attn_tile<<<ga, 256>>>(qh, kh, vh, mask, ah, halves[i]);

        gemm_h<<<gD, 256, GSMEM>>>(ah, lwo, bo + (size_t)i*D_, x, tt, D_, D_, 2);
        ln_kernel<<<M_, 256>>>(tt, ln1g + (size_t)i*D_, ln1b + (size_t)i*D_, x, xh);

        gemm_h<<<gF, 256, GSMEM>>>(xh, lw1, b1 + (size_t)i*FF_, nullptr, hh, FF_, D_, 1);

        gemm_h<<<gD, 256, GSMEM>>>(hh, lw2, b2 + (size_t)i*D_, x, tt, D_, FF_, 2);
        ln_kernel<<<M_, 256>>>(tt, ln2g + (size_t)i*D_, ln2b + (size_t)i*D_, x, xh);
    }

    top_kernel<<<B_, 256>>>(fts, Wtop, btop, out);
}

// round 8
// speedup vs baseline: 4.1445x; 1.0630x over previous
#include <cuda_runtime.h>
#include <cuda_fp16.h>
#include <math.h>
#include <stdint.h>

#define B_ 2
#define S_ 2048
#define D_ 768
#define H_ 12
#define HD_ 64
#define FF_ 3072
#define L_ 12
#define M_ (B_*S_)   // 4096 rows
#define D3_ (3*D_)   // 2304

// ---------------- scratch (device globals; no allocation allowed) ----------
__device__ float g_x[M_*D_];
__device__ float g_t[M_*D_];

__device__ __align__(16) __half g_xh[M_*D_];     // fp16 x (GEMM A input)
__device__ __align__(16) __half g_ah[M_*D_];     // fp16 attention out
__device__ __align__(16) __half g_hh[M_*FF_];    // fp16 gelu out
__device__ __align__(16) __half g_qkv[M_*D3_];   // fused q|k|v rows
// transposed fp16 weights, ALL layers
__device__ __align__(16) __half g_wqkv[L_*D3_*D_];  // [L][2304][768]
__device__ __align__(16) __half g_wo[L_*D_*D_];
__device__ __align__(16) __half g_w1[L_*FF_*D_];    // N=3072,K=768
__device__ __align__(16) __half g_w2[L_*D_*FF_];    // N=768,K=3072
__device__ float g_bqkv[L_*D3_];

// ---------------- PTX helpers (base-target safe) ----------------
__device__ __forceinline__ uint32_t smem_u32(const void* p) {
    uint32_t a;
    asm("{ .reg .u64 t; cvta.to.shared.u64 t, %1; cvt.u32.u64 %0, t; }" : "=r"(a) : "l"(p));
    return a;
}
__device__ __forceinline__ void cp16(uint32_t s, const void* g) {
    asm volatile("cp.async.cg.shared.global [%0], [%1], 16;" :: "r"(s), "l"(g));
}
#define CP_COMMIT()  asm volatile("cp.async.commit_group;" ::: "memory")
#define CP_WAIT(n)   asm volatile("cp.async.wait_group %0;" :: "n"(n) : "memory")

__device__ __forceinline__ void ldm4(uint32_t* r, uint32_t addr) {
    asm volatile("ldmatrix.sync.aligned.m8n8.x4.shared.b16 {%0,%1,%2,%3}, [%4];"
        : "=r"(r[0]), "=r"(r[1]), "=r"(r[2]), "=r"(r[3]) : "r"(addr));
}
__device__ __forceinline__ void mma16816(float* c, const uint32_t* a, uint32_t b0, uint32_t b1) {
    asm volatile("mma.sync.aligned.m16n8k16.row.col.f32.f16.f16.f32 "
        "{%0,%1,%2,%3}, {%4,%5,%6,%7}, {%8,%9}, {%0,%1,%2,%3};"
        : "+f"(c[0]), "+f"(c[1]), "+f"(c[2]), "+f"(c[3])
        : "r"(a[0]), "r"(a[1]), "r"(a[2]), "r"(a[3]), "r"(b0), "r"(b1));
}

// ---------------- batched weight transpose -------------------------------
// W[L][K][N] f32 -> T: per layer (stride lsT), rows [N][K] fp16
__global__ void ttrans_all(const float* __restrict__ W, __half* __restrict__ T,
                           int K, int N, size_t lsW, size_t lsT) {
    __shared__ float t[32][33];
    int li = blockIdx.z;
    const float* Wl = W + (size_t)li * lsW;
    __half* Tl = T + (size_t)li * lsT;
    int k0 = blockIdx.y * 32, n0 = blockIdx.x * 32;
    int tx = threadIdx.x & 31, ty = threadIdx.x >> 5;  // 32 x 8
#pragma unroll
    for (int i = 0; i < 4; i++)
        t[ty + i * 8][tx] = Wl[(size_t)(k0 + ty + i * 8) * N + n0 + tx];
    __syncthreads();
#pragma unroll
    for (int i = 0; i < 4; i++)
        Tl[(size_t)(n0 + ty + i * 8) * K + k0 + tx] = __float2half(t[tx][ty + i * 8]);
}

// concat biases: [L][D] x3 -> [L][3D]
__global__ void bcat_kernel(const float* __restrict__ bq, const float* __restrict__ bk,
                            const float* __restrict__ bv) {
    int i = blockIdx.x * blockDim.x + threadIdx.x;   // over L*3D
    if (i >= L_ * D3_) return;
    int li = i / D3_, r = i % D3_;
    int sec = r / D_, d = r % D_;
    const float* src = sec == 0 ? bq : (sec == 1 ? bk : bv);
    g_bqkv[i] = src[li * D_ + d];
}

// ---------------- mma.sync fp16 GEMM ----------------
// CTA tile 256x128, 8 warps (4x2), warp tile 64x64, BK=32, double-buffered.
// epi: 0 none (f32), 1 gelu (fp16), 2 +residual (f32), 3 bias-only (fp16)
#define PITCH   80
#define TA      (256*PITCH)        // 20480
#define TB      (128*PITCH)        // 10240
#define STAGE   (TA+TB)            // 30720
#define GSMEM   (2*STAGE)          // 61440

__device__ __forceinline__ void load_chunk(uint32_t sbase,
                                           const __half* pA, const __half* pB,
                                           int K, int tid) {
#pragma unroll
    for (int e = 0; e < 4; e++) {       // A: 256 rows x 4 chunks
        int idx = tid + e * 256;
        int r = idx >> 2, ch = idx & 3;
        cp16(sbase + r * PITCH + ch * 16, pA + (size_t)r * K + ch * 8);
    }
#pragma unroll
    for (int e = 0; e < 2; e++) {       // B: 128 rows x 4 chunks
        int idx = tid + e * 256;
        int r = idx >> 2, ch = idx & 3;
        cp16(sbase + TA + r * PITCH + ch * 16, pB + (size_t)r * K + ch * 8);
    }
}

__device__ __forceinline__ float gelu_f(float c) {
    return 0.5f * c * (1.0f + erff(c * 0.70710678118654752f));
}

__global__ void __launch_bounds__(256, 1)
gemm_h(const __half* __restrict__ A, const __half* __restrict__ Bt,
       const float* __restrict__ bias, const float* __restrict__ res,
       void* __restrict__ Cv, int N, int K, int epi) {
    extern __shared__ __align__(16) char smem[];
    uint32_t sb = smem_u32(smem);
    int tid = threadIdx.x, wid = tid >> 5, lane = tid & 31;
    int wm = wid >> 1, wn = wid & 1;       // warp tile: 64 rows x 64 cols
    int m0 = blockIdx.y * 256, n0 = blockIdx.x * 128;

    const __half* pA = A  + (size_t)m0 * K;
    const __half* pB = Bt + (size_t)n0 * K;

    float acc[4][8][4] = {};

    const int NC = K / 32;
    load_chunk(sb, pA, pB, K, tid);
    CP_COMMIT();

    int lrow = lane & 15;
    int lch  = (lane >> 4) * 16;

    for (int c = 0; c < NC; c++) {
        uint32_t st = sb + (c & 1) * STAGE;
        if (c + 1 < NC) {
            load_chunk(sb + ((c + 1) & 1) * STAGE, pA + (c+1)*32, pB + (c+1)*32, K, tid);
            CP_COMMIT();
            CP_WAIT(1);
        } else {
            CP_WAIT(0);
        }
        __syncthreads();

#pragma unroll
        for (int ks = 0; ks < 2; ks++) {
            uint32_t ah[4][4], bh[4][4];
#pragma unroll
            for (int mi = 0; mi < 4; mi++) {
                uint32_t off = (uint32_t)(wm*64 + mi*16 + lrow) * PITCH + ks*32 + lch;
                ldm4(ah[mi], st + off);
            }
#pragma unroll
            for (int np = 0; np < 4; np++) {
                uint32_t off = (uint32_t)(wn*64 + np*16 + lrow) * PITCH + ks*32 + lch;
                ldm4(bh[np], st + TA + off);
            }
#pragma unroll
            for (int mi = 0; mi < 4; mi++)
#pragma unroll
                for (int ni = 0; ni < 8; ni++) {
                    int np = ni >> 1, sel = ni & 1;
                    mma16816(acc[mi][ni], ah[mi], bh[np][sel], bh[np][sel + 2]);
                }
        }
        __syncthreads();
    }

    int qrow = lane >> 2, qcol = (lane & 3) * 2;
#pragma unroll
    for (int mi = 0; mi < 4; mi++) {
#pragma unroll
        for (int ni = 0; ni < 8; ni++) {
            int row = m0 + wm*64 + mi*16 + qrow;
            int col = n0 + wn*64 + ni*8 + qcol;
            float b0 = bias[col], b1 = bias[col + 1];
#pragma unroll
            for (int hh = 0; hh < 2; hh++) {
                int r = row + hh * 8;
                float v0 = acc[mi][ni][hh*2 + 0] + b0;
                float v1 = acc[mi][ni][hh*2 + 1] + b1;
                if (epi == 1) {
                    v0 = gelu_f(v0); v1 = gelu_f(v1);
                    *(__half2*)((__half*)Cv + (size_t)r * N + col) = __floats2half2_rn(v0, v1);
                } else if (epi == 3) {
                    *(__half2*)((__half*)Cv + (size_t)r * N + col) = __floats2half2_rn(v0, v1);
                } else {
                    if (epi == 2) {
                        float2 rr = *(const float2*)(res + (size_t)r * N + col);
                        v0 += rr.x; v1 += rr.y;
                    }
                    *(float2*)((float*)Cv + (size_t)r * N + col) = make_float2(v0, v1);
                }
            }
        }
    }
}

// ---------------- reductions ----------------
__device__ __forceinline__ float warp_max(float v) {
#pragma unroll
    for (int o = 16; o; o >>= 1) v = fmaxf(v, __shfl_xor_sync(0xffffffffu, v, o));
    return v;
}
__device__ __forceinline__ float warp_sum(float v) {
#pragma unroll
    for (int o = 16; o; o >>= 1) v += __shfl_xor_sync(0xffffffffu, v, o);
    return v;
}

// ---------------- warp-per-row layernorm ----------------
// block 256 = 8 warps = 8 rows; lane holds 24 elems of its row.
__global__ void __launch_bounds__(256)
ln_kernel(const float* __restrict__ in, const float* __restrict__ g,
          const float* __restrict__ b, float* __restrict__ out,
          __half* __restrict__ outh) {
    int wid = threadIdx.x >> 5, lane = threadIdx.x & 31;
    int row = blockIdx.x * 8 + wid;
    const float* r = in + (size_t)row * D_;
    float vals[24];
    float s = 0.f, sq = 0.f;
#pragma unroll
    for (int i = 0; i < 24; i++) {
        vals[i] = r[lane + i * 32];
        s += vals[i]; sq += vals[i] * vals[i];
    }
    s = warp_sum(s); sq = warp_sum(sq);
    float mean = s * (1.0f / D_);
    float var = sq * (1.0f / D_) - mean * mean;
    float inv = rsqrtf(var + 1e-5f);
#pragma unroll
    for (int i = 0; i < 24; i++) {
        int d = lane + i * 32;
        float rr = (vals[i] - mean) * inv * g[d] + b[d];
        out[(size_t)row * D_ + d] = rr;
        outh[(size_t)row * D_ + d] = __float2half(rr);
    }
}

__global__ void __launch_bounds__(256)
embed_ln_kernel(const int* __restrict__ ids, const float* __restrict__ we,
                const float* __restrict__ pe, const float* __restrict__ te,
                const float* __restrict__ g, const float* __restrict__ b) {
    int wid = threadIdx.x >> 5, lane = threadIdx.x & 31;
    int row = blockIdx.x * 8 + wid;
    int s_ = row % S_;
    int id = ids[row];
    float vals[24];
    float s = 0.f, sq = 0.f;
#pragma unroll
    for (int i = 0; i < 24; i++) {
        int d = lane + i * 32;
        vals[i] = we[(size_t)id * D_ + d] + pe[(size_t)(s_ + 2) * D_ + d] + te[d];
        s += vals[i]; sq += vals[i] * vals[i];
    }
    s = warp_sum(s); sq = warp_sum(sq);
    float mean = s * (1.0f / D_);
    float var = sq * (1.0f / D_) - mean * mean;
    float inv = rsqrtf(var + 1e-5f);
#pragma unroll
    for (int i = 0; i < 24; i++) {
        int d = lane + i * 32;
        float rr = (vals[i] - mean) * inv * g[d] + b[d];
        g_x[(size_t)row * D_ + d] = rr;
        g_xh[(size_t)row * D_ + d] = __float2half(rr);
    }
}

// ---------------- tiled banded attention (reads fused qkv) ----------------
__global__ void __launch_bounds__(256)
attn_tile(const __half* __restrict__ qkv, const float* __restrict__ mask,
          __half* __restrict__ outh, int half) {
    __shared__ float qs[32][64];
    __shared__ float ks[32][65];
    __shared__ float vs[32][64];
    int tid = threadIdx.x, wid = tid >> 5, lane = tid & 31;
    int qt = blockIdx.x * 32;
    int bh = blockIdx.y;
    int b = bh / H_, h = bh % H_;
    const size_t base = (size_t)b * S_;

#pragma unroll
    for (int i = 0; i < 4; i++) {
        int idx = tid + i * 256;
        int r = idx >> 5, dp = idx & 31;
        float2 f = __half22float2(*(const __half2*)(qkv + (base + qt + r) * D3_ + h * HD_ + 2 * dp));
        qs[r][2*dp] = f.x * 0.125f; qs[r][2*dp+1] = f.y * 0.125f;
    }

    int q0 = wid * 4;
    float m[4], l[4], o0[4], o1[4];
#pragma unroll
    for (int i = 0; i < 4; i++) { m[i] = -1e30f; l[i] = 0.f; o0[i] = 0.f; o1[i] = 0.f; }

    int kt0 = (qt - half) >> 5; if (kt0 < 0) kt0 = 0;
    int kt1 = (qt + 31 + half) >> 5; if (kt1 > S_/32 - 1) kt1 = S_/32 - 1;

    for (int kt = kt0; kt <= kt1; kt++) {
        __syncthreads();
        int j0 = kt * 32;
#pragma unroll
        for (int i = 0; i < 4; i++) {
            int idx = tid + i * 256;
            int r = idx >> 5, dp = idx & 31;
            const __half* rowp = qkv + (base + j0 + r) * D3_ + h * HD_ + 2 * dp;
            float2 fk = __half22float2(*(const __half2*)(rowp + D_));
            float2 fv = __half22float2(*(const __half2*)(rowp + 2 * D_));
            ks[r][2*dp] = fk.x; ks[r][2*dp+1] = fk.y;
            vs[r][2*dp] = fv.x; vs[r][2*dp+1] = fv.y;
        }
        __syncthreads();

        int j = j0 + lane;
        float ka = (1.0f - mask[base + j]) * -1e9f;
        float sc[4] = {0.f, 0.f, 0.f, 0.f};
#pragma unroll
        for (int d = 0; d < 64; d++) {
            float kv = ks[lane][d];
            sc[0] += qs[q0 + 0][d] * kv;
            sc[1] += qs[q0 + 1][d] * kv;
            sc[2] += qs[q0 + 2][d] * kv;
            sc[3] += qs[q0 + 3][d] * kv;
        }
#pragma unroll
        for (int i = 0; i < 4; i++) {
            int qg = qt + q0 + i;
            bool valid = (j >= qg - half) && (j <= qg + half);
            float s = valid ? sc[i] + ka : -1e9f;
            float tmax = warp_max(s);
            float mn = fmaxf(m[i], tmax);
            float scale = __expf(m[i] - mn);
            float p = __expf(s - mn);
            float ls = warp_sum(p);
            m[i] = mn;
            l[i] = l[i] * scale + ls;
            o0[i] *= scale; o1[i] *= scale;
            if (ls != 0.f) {
#pragma unroll 8
                for (int kk = 0; kk < 32; kk++) {
                    float pk = __shfl_sync(0xffffffffu, p, kk);
                    float2 vv = ((const float2*)vs[kk])[lane];
                    o0[i] += pk * vv.x;
                    o1[i] += pk * vv.y;
                }
            }
        }
    }

#pragma unroll
    for (int i = 0; i < 4; i++) {
        int qg = qt + q0 + i;
        float inv = 1.0f / l[i];
        *(__half2*)(outh + (base + qg) * D_ + h * HD_ + 2 * lane) =
            __floats2half2_rn(o0[i] * inv, o1[i] * inv);
    }
}

// ---------------- top head ----------------
__global__ void top_kernel(const float* __restrict__ fts,
                           const float* __restrict__ Wtop,
                           const float* __restrict__ btop,
                           float* __restrict__ out) {
    int b = blockIdx.x;
    int lane = threadIdx.x & 31, wid = threadIdx.x >> 5;
    __shared__ float sw[8];
    const float* cls = g_x + (size_t)b * S_ * D_;
    float part = 0.f;
    for (int d = threadIdx.x; d < D_; d += 256) part += cls[d] * Wtop[d];
    part = warp_sum(part);
    if (lane == 0) sw[wid] = part;
    __syncthreads();
    if (threadIdx.x == 0) {
        float r = 0.f;
#pragma unroll
        for (int i = 0; i < 8; i++) r += sw[i];
        out[b] = r + fts[b] * Wtop[D_] + btop[0];
    }
}

// ---------------- host driver ----------------
extern "C" void kernel_launch(void* const* d_in, const int* in_sizes, int n_in,
                              void* d_out, int out_size) {
    const int*   ids  = (const int*)  d_in[0];
    const float* mask = (const float*)d_in[1];
    const float* fts  = (const float*)d_in[2];
    const float* we   = (const float*)d_in[3];
    const float* pe   = (const float*)d_in[4];
    const float* te   = (const float*)d_in[5];
    const float* ln_eg= (const float*)d_in[6];
    const float* ln_eb= (const float*)d_in[7];
    const float* Wq   = (const float*)d_in[8];
    const float* bq   = (const float*)d_in[9];
    const float* Wk   = (const float*)d_in[10];
    const float* bk   = (const float*)d_in[11];
    const float* Wv   = (const float*)d_in[12];
    const float* bv   = (const float*)d_in[13];
    const float* Wo   = (const float*)d_in[14];
    const float* bo   = (const float*)d_in[15];
    const float* ln1g = (const float*)d_in[16];
    const float* ln1b = (const float*)d_in[17];
    const float* W1   = (const float*)d_in[18];
    const float* b1   = (const float*)d_in[19];
    const float* W2   = (const float*)d_in[20];
    const float* b2   = (const float*)d_in[21];
    const float* ln2g = (const float*)d_in[22];
    const float* ln2b = (const float*)d_in[23];
    const float* Wtop = (const float*)d_in[24];
    const float* btop = (const float*)d_in[25];
    float* out = (float*)d_out;

    float *x, *tt, *bqkv;
    cudaGetSymbolAddress((void**)&x,  g_x);
    cudaGetSymbolAddress((void**)&tt, g_t);
    cudaGetSymbolAddress((void**)&bqkv, g_bqkv);

    __half *xh, *ah, *hh, *qkv, *wqkv, *wo, *w1, *w2;
    cudaGetSymbolAddress((void**)&xh, g_xh);
    cudaGetSymbolAddress((void**)&ah, g_ah);
    cudaGetSymbolAddress((void**)&hh, g_hh);
    cudaGetSymbolAddress((void**)&qkv, g_qkv);
    cudaGetSymbolAddress((void**)&wqkv, g_wqkv);
    cudaGetSymbolAddress((void**)&wo, g_wo);
    cudaGetSymbolAddress((void**)&w1, g_w1);
    cudaGetSymbolAddress((void**)&w2, g_w2);

    cudaFuncSetAttribute(gemm_h, cudaFuncAttributeMaxDynamicSharedMemorySize, GSMEM);

    static const int halves[L_] = {16,16,32,32,64,64,128,128,256,256,256,256};

    embed_ln_kernel<<<M_/8, 256>>>(ids, we, pe, te, ln_eg, ln_eb);

    // weight prep (batched over layers)
    dim3 tD(D_ / 32, D_ / 32, L_);
    dim3 t1(FF_ / 32, D_ / 32, L_);
    dim3 t2(D_ / 32, FF_ / 32, L_);
    size_t lsD = (size_t)D_ * D_, lsQKV = (size_t)D3_ * D_;
    ttrans_all<<<tD, 256>>>(Wq, wqkv + 0 * lsD, D_, D_, lsD, lsQKV);
    ttrans_all<<<tD, 256>>>(Wk, wqkv + 1 * lsD, D_, D_, lsD, lsQKV);
    ttrans_all<<<tD, 256>>>(Wv, wqkv + 2 * lsD, D_, D_, lsD, lsQKV);
    ttrans_all<<<tD, 256>>>(Wo, wo, D_, D_, lsD, lsD);
    ttrans_all<<<t1, 256>>>(W1, w1, D_, FF_, (size_t)D_*FF_, (size_t)FF_*D_);
    ttrans_all<<<t2, 256>>>(W2, w2, FF_, D_, (size_t)FF_*D_, (size_t)D_*FF_);
    bcat_kernel<<<(L_*D3_ + 255)/256, 256>>>(bq, bk, bv);

    dim3 gQKV(D3_ / 128, M_ / 256); // (18, 16) = 288 CTAs
    dim3 gD(D_ / 128, M_ / 256);    // (6, 16)
    dim3 gF(FF_ / 128, M_ / 256);   // (24, 16)
    dim3 ga(S_ / 32, B_ * H_);      // (64, 24)

    for (int i = 0; i < L_; i++) {
        __half* lwqkv = wqkv + (size_t)i * lsQKV;
        __half* lwo = wo + (size_t)i * lsD;
        __half* lw1 = w1 + (size_t)i * FF_ * D_;
        __half* lw2 = w2 + (size_t)i * D_ * FF_;

        gemm_h<<<gQKV, 256, GSMEM>>>(xh, lwqkv, bqkv + (size_t)i*D3_, nullptr, qkv, D3_, D_, 3);

        attn_tile<<<ga, 256>>>(qkv, mask, ah, halves[i]);

        gemm_h<<<gD, 256, GSMEM>>>(ah, lwo, bo + (size_t)i*D_, x, tt, D_, D_, 2);
        ln_kernel<<<M_/8, 256>>>(tt, ln1g + (size_t)i*D_, ln1b + (size_t)i*D_, x, xh);

        gemm_h<<<gF, 256, GSMEM>>>(xh, lw1, b1 + (size_t)i*FF_, nullptr, hh, FF_, D_, 1);

        gemm_h<<<gD, 256, GSMEM>>>(hh, lw2, b2 + (size_t)i*D_, x, tt, D_, FF_, 2);
        ln_kernel<<<M_/8, 256>>>(tt, ln2g + (size_t)i*D_, ln2b + (size_t)i*D_, x, xh);
    }

    top_kernel<<<B_, 256>>>(fts, Wtop, btop, out);
}